// round 10
// baseline (speedup 1.0000x reference)
#include <cuda_runtime.h>
#include <math.h>
#include <stdint.h>

// Problem constants
constexpr int T_ = 64;
constexpr int B_ = 256;
constexpr int NITEMS = 100000;
constexpr int E_ = 128;
constexpr int H_ = 512;
constexpr int NH_ = 8;
constexpr int G4_ = 4 * H_;   // 2048
constexpr int TB_ = T_ * B_;  // 16384

// ---------------- scratch (device globals) ----------------------------------
__device__ float g_embs[TB_ * E_];             // tf32-rounded emb[x]^2, k-pair-permuted
__device__ float g_bsum[G4_];
__device__ float g_hseq[(T_ + 1) * B_ * H_];   // tf32-rounded h per step, k-pair-permuted
__device__ float g_lstm_out[TB_ * H_];         // (B,T,H), tf32-rounded, UNpermuted
__device__ float g_QKV[TB_ * 3 * H_];          // [TB][1536]: Q|K|V
__device__ float g_wout[TB_ * H_];
__device__ float g_mho[TB_ * H_];
__device__ float g_ae[B_ * E_];
__device__ __align__(128) unsigned int g_flags[4][32];  // [group][block-in-group]

// ---------------- helpers ----------------------------------------------------
__device__ __forceinline__ float tf32r(float x) {
    uint32_t u;
    asm("cvt.rna.tf32.f32 %0, %1;" : "=r"(u) : "f"(x));
    return __uint_as_float(u);
}

__device__ __forceinline__ void mma_tf32(float c[4],
                                         float a0, float a1, float a2, float a3,
                                         float b0, float b1) {
    asm volatile(
        "mma.sync.aligned.m16n8k8.row.col.f32.tf32.tf32.f32 "
        "{%0,%1,%2,%3},{%4,%5,%6,%7},{%8,%9},{%0,%1,%2,%3};"
        : "+f"(c[0]), "+f"(c[1]), "+f"(c[2]), "+f"(c[3])
        : "r"(__float_as_uint(a0)), "r"(__float_as_uint(a1)),
          "r"(__float_as_uint(a2)), "r"(__float_as_uint(a3)),
          "r"(__float_as_uint(b0)), "r"(__float_as_uint(b1)));
}

__device__ __forceinline__ float sigmoidf_(float x) {
    return 1.f / (1.f + expf(-x));
}

__device__ __forceinline__ void cp16(uint32_t d, const float* s) {
    asm volatile("cp.async.cg.shared.global [%0], [%1], 16;" :: "r"(d), "l"(s));
}
__device__ __forceinline__ void cp_commit() {
    asm volatile("cp.async.commit_group;");
}
template<int N>
__device__ __forceinline__ void cp_wait() {
    asm volatile("cp.async.wait_group %0;" :: "n"(N));
}

// k-pair permutation within each 8-col group: k -> (k&3)*2 + ((k>>2)&1)
__device__ __forceinline__ int kperm(int k) {
    return (k & ~7) | (((k & 3) << 1) | ((k >> 2) & 1));
}

// ---------------- small kernels ---------------------------------------------
__global__ void zero_init_kernel() {
    int i = blockIdx.x * blockDim.x + threadIdx.x;
    if (i < B_ * H_) g_hseq[i] = 0.f;
    if (i < 128) ((unsigned*)g_flags)[i] = 0u;
}

__global__ void bias_sum_kernel(const float* __restrict__ b_ih,
                                const float* __restrict__ b_hh) {
    int i = blockIdx.x * blockDim.x + threadIdx.x;
    if (i < G4_) g_bsum[i] = b_ih[i] + b_hh[i];
}

// embs[row][8q+2r, 8q+2r+1] = tf32r(emb[x[row]][8q+r]^2), tf32r(...[8q+r+4]^2)
__global__ void gather_square_kernel(const int* __restrict__ x,
                                     const float* __restrict__ emb) {
    int fi = blockIdx.x * blockDim.x + threadIdx.x;   // pair index
    int row = fi >> 6;                // 64 pairs per row (E=128)
    int p = fi & 63;
    int q = p >> 2, r = p & 3;
    int id = x[row];
    const float* src = emb + (size_t)id * E_ + 8 * q + r;
    float a0 = src[0], a1 = src[4];
    float2 o = make_float2(tf32r(a0 * a0), tf32r(a1 * a1));
    *(float2*)&g_embs[(size_t)row * E_ + 8 * q + 2 * r] = o;
}

// ---------------- tf32 tensor-core GEMM: C = A(MxK) W(NxK)^T + bias ----------
template<bool CHECKN>
__global__ __launch_bounds__(256, 2)
void gemm_tf32(const float* __restrict__ A, const float* __restrict__ W,
               const float* __restrict__ bias, float* __restrict__ C,
               int M, int N, int K) {
    __shared__ __align__(16) float As[2][128][20];
    __shared__ __align__(16) float Bs[2][128][20];

    const int tid = threadIdx.x;
    const int lane = tid & 31;
    const int wid = tid >> 5;
    const int wm = (wid & 3) * 32;
    const int wn = (wid >> 2) * 64;
    const int bm = blockIdx.y * 128;
    const int bn = blockIdx.x * 128;
    const int lr = tid >> 1;
    const int lk = (tid & 1) * 8;

    int wrow = bn + lr;
    bool wok = true;
    if (CHECKN) { wok = (wrow < N); if (!wok) wrow = N - 1; }
    const float* Ap = A + (size_t)(bm + lr) * K + lk;
    const float* Wp = W + (size_t)wrow * K + lk;

    float acc[2][8][4];
#pragma unroll
    for (int mt = 0; mt < 2; mt++)
#pragma unroll
        for (int nt = 0; nt < 8; nt++)
#pragma unroll
            for (int q = 0; q < 4; q++) acc[mt][nt][q] = 0.f;

    const int gq = lane >> 2;
    const int tg = lane & 3;

    float4 pa0, pa1, pb0, pb1;
    pa0 = *(const float4*)(Ap);
    pa1 = *(const float4*)(Ap + 4);
    if (!CHECKN || wok) {
        pb0 = *(const float4*)(Wp);
        pb1 = *(const float4*)(Wp + 4);
    } else { pb0 = make_float4(0,0,0,0); pb1 = pb0; }

#define GEMM_STAGE(BUF)                                                       \
    {                                                                         \
        float4 ca0 = make_float4(tf32r(pa0.x), tf32r(pa0.y), tf32r(pa0.z), tf32r(pa0.w)); \
        float4 ca1 = make_float4(tf32r(pa1.x), tf32r(pa1.y), tf32r(pa1.z), tf32r(pa1.w)); \
        float4 cb0 = make_float4(tf32r(pb0.x), tf32r(pb0.y), tf32r(pb0.z), tf32r(pb0.w)); \
        float4 cb1 = make_float4(tf32r(pb1.x), tf32r(pb1.y), tf32r(pb1.z), tf32r(pb1.w)); \
        *(float4*)&As[BUF][lr][lk]     = ca0;                                 \
        *(float4*)&As[BUF][lr][lk + 4] = ca1;                                 \
        *(float4*)&Bs[BUF][lr][lk]     = cb0;                                 \
        *(float4*)&Bs[BUF][lr][lk + 4] = cb1;                                 \
    }

#define GEMM_COMPUTE(BUF)                                                     \
    _Pragma("unroll")                                                         \
    for (int ks = 0; ks < 16; ks += 8) {                                      \
        float a[2][4];                                                        \
        float b[8][2];                                                        \
        _Pragma("unroll")                                                     \
        for (int mt = 0; mt < 2; mt++) {                                      \
            int r = wm + mt * 16 + gq;                                        \
            int c = ks + tg;                                                  \
            a[mt][0] = As[BUF][r][c];                                         \
            a[mt][1] = As[BUF][r + 8][c];                                     \
            a[mt][2] = As[BUF][r][c + 4];                                     \
            a[mt][3] = As[BUF][r + 8][c + 4];                                 \
        }                                                                     \
        _Pragma("unroll")                                                     \
        for (int nt = 0; nt < 8; nt++) {                                      \
            int n = wn + nt * 8 + gq;                                         \
            b[nt][0] = Bs[BUF][n][ks + tg];                                   \
            b[nt][1] = Bs[BUF][n][ks + tg + 4];                               \
        }                                                                     \
        _Pragma("unroll")                                                     \
        for (int mt = 0; mt < 2; mt++)                                        \
            _Pragma("unroll")                                                 \
            for (int nt = 0; nt < 8; nt++)                                    \
                mma_tf32(acc[mt][nt], a[mt][0], a[mt][1], a[mt][2], a[mt][3], \
                         b[nt][0], b[nt][1]);                                 \
    }

    GEMM_STAGE(0)
    __syncthreads();

    int buf = 0;
    for (int k0 = 16; k0 < K; k0 += 16) {
        pa0 = *(const float4*)(Ap + k0);
        pa1 = *(const float4*)(Ap + k0 + 4);
        if (!CHECKN || wok) {
            pb0 = *(const float4*)(Wp + k0);
            pb1 = *(const float4*)(Wp + k0 + 4);
        } else { pb0 = make_float4(0,0,0,0); pb1 = pb0; }
        if (buf == 0) { GEMM_COMPUTE(0) GEMM_STAGE(1) }
        else          { GEMM_COMPUTE(1) GEMM_STAGE(0) }
        __syncthreads();
        buf ^= 1;
    }
    if (buf == 0) { GEMM_COMPUTE(0) } else { GEMM_COMPUTE(1) }

#pragma unroll
    for (int mt = 0; mt < 2; mt++) {
        int r = bm + wm + mt * 16 + gq;
#pragma unroll
        for (int nt = 0; nt < 8; nt++) {
            int cgl = bn + wn + nt * 8 + 2 * tg;
            if (CHECKN && cgl >= N) continue;
            float bv0 = 0.f, bv1 = 0.f;
            if (bias) { bv0 = bias[cgl]; bv1 = bias[cgl + 1]; }
            *(float2*)&C[(size_t)r * N + cgl] =
                make_float2(acc[mt][nt][0] + bv0, acc[mt][nt][1] + bv1);
            *(float2*)&C[(size_t)(r + 8) * N + cgl] =
                make_float2(acc[mt][nt][2] + bv0, acc[mt][nt][3] + bv1);
        }
    }
#undef GEMM_STAGE
#undef GEMM_COMPUTE
}

// ---------------- fused QKV GEMM: C[TB][1536] = A @ [wq|wk|wv]^T + bias ------
__global__ __launch_bounds__(256, 2)
void gemm_qkv(const float* __restrict__ A,
              const float* __restrict__ wq, const float* __restrict__ wk,
              const float* __restrict__ wv,
              const float* __restrict__ bq, const float* __restrict__ bk,
              const float* __restrict__ bv,
              float* __restrict__ C) {
    __shared__ __align__(16) float As[2][128][20];
    __shared__ __align__(16) float Bs[2][128][20];
    constexpr int K = H_, N = 3 * H_;

    const int tid = threadIdx.x;
    const int lane = tid & 31;
    const int wid = tid >> 5;
    const int wm = (wid & 3) * 32;
    const int wn = (wid >> 2) * 64;
    const int bm = blockIdx.y * 128;
    const int bn = blockIdx.x * 128;
    const int lr = tid >> 1;
    const int lk = (tid & 1) * 8;

    const int wrow = bn + lr;
    const int sel = wrow >> 9;
    const int wl = wrow & 511;
    const float* Wbase = (sel == 0) ? wq : ((sel == 1) ? wk : wv);
    const float* Ap = A + (size_t)(bm + lr) * K + lk;
    const float* Wp = Wbase + (size_t)wl * K + lk;

    float acc[2][8][4];
#pragma unroll
    for (int mt = 0; mt < 2; mt++)
#pragma unroll
        for (int nt = 0; nt < 8; nt++)
#pragma unroll
            for (int q = 0; q < 4; q++) acc[mt][nt][q] = 0.f;

    const int gq = lane >> 2;
    const int tg = lane & 3;

    float4 pa0, pa1, pb0, pb1;
    pa0 = *(const float4*)(Ap);
    pa1 = *(const float4*)(Ap + 4);
    pb0 = *(const float4*)(Wp);
    pb1 = *(const float4*)(Wp + 4);

#define QKV_STAGE(BUF)                                                        \
    {                                                                         \
        float4 ca0 = make_float4(tf32r(pa0.x), tf32r(pa0.y), tf32r(pa0.z), tf32r(pa0.w)); \
        float4 ca1 = make_float4(tf32r(pa1.x), tf32r(pa1.y), tf32r(pa1.z), tf32r(pa1.w)); \
        float4 cb0 = make_float4(tf32r(pb0.x), tf32r(pb0.y), tf32r(pb0.z), tf32r(pb0.w)); \
        float4 cb1 = make_float4(tf32r(pb1.x), tf32r(pb1.y), tf32r(pb1.z), tf32r(pb1.w)); \
        *(float4*)&As[BUF][lr][lk]     = ca0;                                 \
        *(float4*)&As[BUF][lr][lk + 4] = ca1;                                 \
        *(float4*)&Bs[BUF][lr][lk]     = cb0;                                 \
        *(float4*)&Bs[BUF][lr][lk + 4] = cb1;                                 \
    }

#define QKV_COMPUTE(BUF)                                                      \
    _Pragma("unroll")                                                         \
    for (int ks = 0; ks < 16; ks += 8) {                                      \
        float a[2][4];                                                        \
        float b[8][2];                                                        \
        _Pragma("unroll")                                                     \
        for (int mt = 0; mt < 2; mt++) {                                      \
            int r = wm + mt * 16 + gq;                                        \
            int c = ks + tg;                                                  \
            a[mt][0] = As[BUF][r][c];                                         \
            a[mt][1] = As[BUF][r + 8][c];                                     \
            a[mt][2] = As[BUF][r][c + 4];                                     \
            a[mt][3] = As[BUF][r + 8][c + 4];                                 \
        }                                                                     \
        _Pragma("unroll")                                                     \
        for (int nt = 0; nt < 8; nt++) {                                      \
            int n = wn + nt * 8 + gq;                                         \
            b[nt][0] = Bs[BUF][n][ks + tg];                                   \
            b[nt][1] = Bs[BUF][n][ks + tg + 4];                               \
        }                                                                     \
        _Pragma("unroll")                                                     \
        for (int mt = 0; mt < 2; mt++)                                        \
            _Pragma("unroll")                                                 \
            for (int nt = 0; nt < 8; nt++)                                    \
                mma_tf32(acc[mt][nt], a[mt][0], a[mt][1], a[mt][2], a[mt][3], \
                         b[nt][0], b[nt][1]);                                 \
    }

    QKV_STAGE(0)
    __syncthreads();

    int buf = 0;
    for (int k0 = 16; k0 < K; k0 += 16) {
        pa0 = *(const float4*)(Ap + k0);
        pa1 = *(const float4*)(Ap + k0 + 4);
        pb0 = *(const float4*)(Wp + k0);
        pb1 = *(const float4*)(Wp + k0 + 4);
        if (buf == 0) { QKV_COMPUTE(0) QKV_STAGE(1) }
        else          { QKV_COMPUTE(1) QKV_STAGE(0) }
        __syncthreads();
        buf ^= 1;
    }
    if (buf == 0) { QKV_COMPUTE(0) } else { QKV_COMPUTE(1) }

#pragma unroll
    for (int mt = 0; mt < 2; mt++) {
        int r = bm + wm + mt * 16 + gq;
#pragma unroll
        for (int nt = 0; nt < 8; nt++) {
            int cgl = bn + wn + nt * 8 + 2 * tg;
            int selc = cgl >> 9;
            int lc = cgl & 511;
            const float* bb = (selc == 0) ? bq : ((selc == 1) ? bk : bv);
            float bv0 = bb[lc], bv1 = bb[lc + 1];
            *(float2*)&C[(size_t)r * N + cgl] =
                make_float2(acc[mt][nt][0] + bv0, acc[mt][nt][1] + bv1);
            *(float2*)&C[(size_t)(r + 8) * N + cgl] =
                make_float2(acc[mt][nt][2] + bv0, acc[mt][nt][3] + bv1);
        }
    }
#undef QKV_STAGE
#undef QKV_COMPUTE
}

// ---------------- persistent tensor-core LSTM --------------------------------
// k-pair-permuted layouts -> LDS.64 fragment loads; flag barrier; e-overlap.
constexpr int WHH_STR = 516;
constexpr int WIH_STR = 132;
constexpr int HS_STR  = 68;
constexpr int WHH_FLOATS = 64 * WHH_STR;
constexpr int WIH_FLOATS = 64 * WIH_STR;
constexpr int STG_FLOATS = 64 * HS_STR;
constexpr int LSTM_SMEM_BYTES = (WHH_FLOATS + WIH_FLOATS + 3 * STG_FLOATS) * 4;

// fragment loads from pair-permuted data: cols (tg, tg+4) at slot 2*tg
__device__ __forceinline__ void lstm_comp(const float* HS, const float* WS,
                                          int wstr, int coff,
                                          int wm, int wn, int gq, int tg,
                                          float (&acc)[2][2][4]) {
#pragma unroll
    for (int ks = 0; ks < 64; ks += 8) {
        float a[2][4];
        float bf[2][2];
#pragma unroll
        for (int mt = 0; mt < 2; mt++) {
            int r = wm + mt * 16 + gq;
            float2 lo = *(const float2*)&HS[r * HS_STR + ks + 2 * tg];
            float2 hi = *(const float2*)&HS[(r + 8) * HS_STR + ks + 2 * tg];
            a[mt][0] = lo.x; a[mt][2] = lo.y;
            a[mt][1] = hi.x; a[mt][3] = hi.y;
        }
#pragma unroll
        for (int nt = 0; nt < 2; nt++) {
            int n = wn + nt * 8 + gq;
            float2 w2 = *(const float2*)&WS[n * wstr + coff + ks + 2 * tg];
            bf[nt][0] = w2.x; bf[nt][1] = w2.y;
        }
#pragma unroll
        for (int mt = 0; mt < 2; mt++)
#pragma unroll
            for (int nt = 0; nt < 2; nt++)
                mma_tf32(acc[mt][nt], a[mt][0], a[mt][1], a[mt][2], a[mt][3],
                         bf[nt][0], bf[nt][1]);
    }
}

__global__ __launch_bounds__(256, 1)
void lstm_persistent(const float* __restrict__ w_ih,    // (4H,E)
                     const float* __restrict__ w_hh,    // (4H,H)
                     const int* __restrict__ lengths) {
    extern __shared__ __align__(16) float dsm[];
    float* ws_hh = dsm;
    float* ws_ih = ws_hh + WHH_FLOATS;
    float* stage = ws_ih + WIH_FLOATS;
    float* ps    = stage + 1 * STG_FLOATS;     // alias buffer 1

    const int tid = threadIdx.x;
    const int lane = tid & 31;
    const int wid = tid >> 5;
    const int wm = (wid & 1) * 32;
    const int wn = (wid >> 1) * 16;
    const int blkInGrp = blockIdx.x & 31;
    const int j0 = blkInGrp * 16;
    const int b0 = (blockIdx.x >> 5) * 64;
    const int grp = blockIdx.x >> 5;

    const int gq = lane >> 2;
    const int tg = lane & 3;

    // load w_hh slice, tf32 + pair-permuted (slots: k4&4 ? odd : even, stride 2)
    for (int idx = tid; idx < 64 * 128; idx += 256) {
        int n = idx >> 7;
        int k4 = (idx & 127) * 4;
        int g = n >> 4, jl = n & 15;
        float4 v = *(const float4*)(w_hh + (size_t)(g * H_ + j0 + jl) * H_ + k4);
        float* dst = ws_hh + n * WHH_STR + (k4 & ~7) + ((k4 & 4) ? 1 : 0);
        dst[0] = tf32r(v.x); dst[2] = tf32r(v.y);
        dst[4] = tf32r(v.z); dst[6] = tf32r(v.w);
    }
    // load w_ih slice, same permutation
    for (int idx = tid; idx < 64 * 32; idx += 256) {
        int n = idx >> 5;
        int k4 = (idx & 31) * 4;
        int g = n >> 4, jl = n & 15;
        float4 v = *(const float4*)(w_ih + (size_t)(g * H_ + j0 + jl) * E_ + k4);
        float* dst = ws_ih + n * WIH_STR + (k4 & ~7) + ((k4 & 4) ? 1 : 0);
        dst[0] = tf32r(v.x); dst[2] = tf32r(v.y);
        dst[4] = tf32r(v.z); dst[6] = tf32r(v.w);
    }
    __syncthreads();

    // staging indices: row 0..63, cg 0..3 (16 cols = 4x16B each)
    const int row = tid >> 2;
    const int cg = tid & 3;
    const float* e_base = g_embs + (size_t)(b0 + row) * E_ + cg * 16;
    const float* h_base = g_hseq + (size_t)(b0 + row) * H_ + cg * 16;

    uint32_t stage_u32 = (uint32_t)__cvta_generic_to_shared(stage);
    uint32_t stg_u32[3];
#pragma unroll
    for (int bff = 0; bff < 3; bff++)
        stg_u32[bff] = stage_u32 + (uint32_t)(bff * STG_FLOATS + row * HS_STR + cg * 16) * 4u;

    // epilogue cell mapping
    int lenp[4];
    float bi[4], bfo[4], bg[4], bo4[4];
    float creg[4];
    int pjp[4];
#pragma unroll
    for (int p = 0; p < 4; p++) {
        int idx = tid + p * 256;
        int jloc = idx & 15;
        int bl = idx >> 4;
        lenp[p] = lengths[b0 + bl];
        int j = j0 + jloc;
        pjp[p] = kperm(j);
        bi[p]  = g_bsum[j];
        bfo[p] = g_bsum[H_ + j];
        bg[p]  = g_bsum[2 * H_ + j];
        bo4[p] = g_bsum[3 * H_ + j];
        creg[p] = 0.f;
    }

    auto issue16 = [&](const float* s, uint32_t dst) {
        cp16(dst, s); cp16(dst + 16, s + 4);
        cp16(dst + 32, s + 8); cp16(dst + 48, s + 12);
        cp_commit();
    };

    float accE[2][2][4];
    auto compute_e = [&](int tt) {
#pragma unroll
        for (int mt = 0; mt < 2; mt++)
#pragma unroll
            for (int nt = 0; nt < 2; nt++)
#pragma unroll
                for (int q = 0; q < 4; q++) accE[mt][nt][q] = 0.f;
        const float* e_t = e_base + (size_t)tt * B_ * E_;
        issue16(e_t, stg_u32[0]);
        issue16(e_t + 64, stg_u32[1]);
        cp_wait<1>(); __syncthreads();
        lstm_comp(stage, ws_ih, WIH_STR, 0, wm, wn, gq, tg, accE);
        cp_wait<0>(); __syncthreads();
        lstm_comp(stage + STG_FLOATS, ws_ih, WIH_STR, 64, wm, wn, gq, tg, accE);
    };

    compute_e(0);

    for (int t = 0; t < T_; t++) {
        float acc[2][2][4];
#pragma unroll
        for (int mt = 0; mt < 2; mt++)
#pragma unroll
            for (int nt = 0; nt < 2; nt++)
#pragma unroll
                for (int q = 0; q < 4; q++) acc[mt][nt][q] = accE[mt][nt][q];

        // wait until all blocks in group have published h_t (flags >= t)
        if (t > 0) {
            if (tid < 32) {
                volatile unsigned* f = &g_flags[grp][lane];
                unsigned tgt = (unsigned)t;
                for (;;) {
                    unsigned v = *f;
                    if (__all_sync(0xffffffffu, v >= tgt)) break;
                    __nanosleep(64);
                }
            }
            __syncthreads();
        } else {
            __syncthreads();   // protect e1 compute before buffer reuse
        }

        const float* h_t = h_base + (size_t)t * B_ * H_;
        // h chunk c (c=0..7) lives in buffer (c+2)%3
        issue16(h_t, stg_u32[2]);          // h0 -> buf2
        issue16(h_t + 64, stg_u32[0]);     // h1 -> buf0

#pragma unroll
        for (int c = 0; c < 8; c++) {
            if (c < 7) cp_wait<1>(); else cp_wait<0>();
            __syncthreads();
            if (c + 2 < 8) issue16(h_t + (c + 2) * 64, stg_u32[(c + 4) % 3]);
            lstm_comp(stage + ((c + 2) % 3) * STG_FLOATS, ws_hh, WHH_STR,
                      c * 64, wm, wn, gq, tg, acc);
        }

        // preacts -> shared (ps aliases buffer 1: last used by h5, done)
        __syncthreads();
#pragma unroll
        for (int mt = 0; mt < 2; mt++) {
            int r = wm + mt * 16 + gq;
#pragma unroll
            for (int nt = 0; nt < 2; nt++) {
                int c = wn + nt * 8 + 2 * tg;
                *(float2*)&ps[r * HS_STR + c] = make_float2(acc[mt][nt][0], acc[mt][nt][1]);
                *(float2*)&ps[(r + 8) * HS_STR + c] = make_float2(acc[mt][nt][2], acc[mt][nt][3]);
            }
        }
        __syncthreads();

        // gate epilogue: h written tf32-rounded, pair-permuted into g_hseq
        float* hout = g_hseq + (size_t)(t + 1) * B_ * H_;
#pragma unroll
        for (int p = 0; p < 4; p++) {
            int idx = tid + p * 256;
            int jloc = idx & 15;
            int bl = idx >> 4;
            int b = b0 + bl;
            int j = j0 + jloc;
            float gi = sigmoidf_(ps[bl * HS_STR + jloc]      + bi[p]);
            float gf = sigmoidf_(ps[bl * HS_STR + 16 + jloc] + bfo[p]);
            float gg = tanhf(    ps[bl * HS_STR + 32 + jloc] + bg[p]);
            float go = sigmoidf_(ps[bl * HS_STR + 48 + jloc] + bo4[p]);
            float cn = gf * creg[p] + gi * gg;
            creg[p] = cn;
            float hn = tf32r(go * tanhf(cn));
            hout[(size_t)b * H_ + pjp[p]] = hn;
            g_lstm_out[(size_t)(b * T_ + t) * H_ + j] = (t < lenp[p]) ? hn : 0.f;
        }
        __syncthreads();

        // publish h_{t+1}
        if (tid == 0) {
            __threadfence();
            *(volatile unsigned*)&g_flags[grp][blkInGrp] = (unsigned)(t + 1);
        }

        // overlap: compute e-part of step t+1 while other blocks finish
        if (t < T_ - 1) compute_e(t + 1);
    }
}

// ---------------- attention: one block per (b, head), QKV packed ------------
__global__ __launch_bounds__(256)
void attention_kernel(const float* __restrict__ QKV,
                      const int* __restrict__ lengths,
                      float* __restrict__ Wout) {
    __shared__ float qs[64 * 64];
    __shared__ float ks[64 * 64];
    __shared__ float ss[64 * 64];
    const int b = blockIdx.x, nh = blockIdx.y;
    const int tid = threadIdx.x;
    const int len = lengths[b];
    const size_t qkvbase = ((size_t)b * 64) * 1536 + nh * 64;
    const size_t obase = ((size_t)b * 64) * 512 + nh * 64;

#pragma unroll
    for (int l = 0; l < 4; l++) {
        int fidx = tid + (l << 8);
        int r = fidx & 63, c4 = fidx >> 6;
        float4 qv = *(const float4*)(QKV + qkvbase + (size_t)r * 1536 + c4 * 4);
        float4 kv = *(const float4*)(QKV + qkvbase + 512 + (size_t)r * 1536 + c4 * 4);
        qs[(c4 * 4 + 0) * 64 + r] = qv.x; qs[(c4 * 4 + 1) * 64 + r] = qv.y;
        qs[(c4 * 4 + 2) * 64 + r] = qv.z; qs[(c4 * 4 + 3) * 64 + r] = qv.w;
        ks[(c4 * 4 + 0) * 64 + r] = kv.x; ks[(c4 * 4 + 1) * 64 + r] = kv.y;
        ks[(c4 * 4 + 2) * 64 + r] = kv.z; ks[(c4 * 4 + 3) * 64 + r] = kv.w;
    }
    __syncthreads();

    const int tx = tid & 15, ty = tid >> 4;
    const int r0 = ty * 4, c0 = tx * 4;
    float acc[4][4];
#pragma unroll
    for (int i = 0; i < 4; i++)
#pragma unroll
        for (int j = 0; j < 4; j++) acc[i][j] = 0.f;

#pragma unroll 8
    for (int k = 0; k < 64; k++) {
        float4 aq = *(const float4*)&qs[k * 64 + r0];
        float4 bk = *(const float4*)&ks[k * 64 + c0];
        float a[4] = {aq.x, aq.y, aq.z, aq.w};
        float bb[4] = {bk.x, bk.y, bk.z, bk.w};
#pragma unroll
        for (int i = 0; i < 4; i++)
#pragma unroll
            for (int j = 0; j < 4; j++) acc[i][j] += a[i] * bb[j];
    }
#pragma unroll
    for (int i = 0; i < 4; i++)
#pragma unroll
        for (int j = 0; j < 4; j++) {
            int c = c0 + j;
            ss[(r0 + i) * 64 + c] = (c < len) ? acc[i][j] * 0.125f : -1e30f;
        }
    __syncthreads();

    float* vs = qs;
#pragma unroll
    for (int l = 0; l < 4; l++) {
        int fidx = tid + (l << 8);
        int r = fidx >> 4, c4 = fidx & 15;
        ((float4*)vs)[fidx] =
            *(const float4*)(QKV + qkvbase + 1024 + (size_t)r * 1536 + c4 * 4);
    }
    if (tid < 64) {
        float m = -1e30f;
#pragma unroll 8
        for (int c = 0; c < 64; c++) m = fmaxf(m, ss[tid * 64 + c]);
        float s = 0.f;
#pragma unroll 8
        for (int c = 0; c < 64; c++) {
            float e = expf(ss[tid * 64 + c] - m);
            ss[tid * 64 + c] = e;
            s += e;
        }
        float inv = 1.f / s;
#pragma unroll 8
        for (int c = 0; c < 64; c++) ss[tid * 64 + c] *= inv;
    }
    __syncthreads();

    float o[4][4];
#pragma unroll
    for (int i = 0; i < 4; i++)
#pragma unroll
        for (int j = 0; j < 4; j++) o[i][j] = 0.f;
#pragma unroll 8
    for (int k = 0; k < 64; k++) {
        float a[4];
#pragma unroll
        for (int i = 0; i < 4; i++) a[i] = ss[(r0 + i) * 64 + k];
        float4 vv4 = *(const float4*)&vs[k * 64 + c0];
        float vv[4] = {vv4.x, vv4.y, vv4.z, vv4.w};
#pragma unroll
        for (int i = 0; i < 4; i++)
#pragma unroll
            for (int j = 0; j < 4; j++) o[i][j] += a[i] * vv[j];
    }
#pragma unroll
    for (int i = 0; i < 4; i++) {
        float4 ov = make_float4(o[i][0], o[i][1], o[i][2], o[i][3]);
        *(float4*)(Wout + obase + (size_t)(r0 + i) * 512 + c0) = ov;
    }
}

// ---------------- fused meanpool + hidden_to_embedding ----------------------
__global__ __launch_bounds__(128)
void pool_h2e_kernel(const float* __restrict__ w_h2e,
                     const float* __restrict__ b_h2e) {
    __shared__ float sp[H_];
    const int b = blockIdx.x;
    const int tid = threadIdx.x;
    float s0 = 0.f, s1 = 0.f, s2 = 0.f, s3 = 0.f;
    const float* src = g_mho + (size_t)b * 64 * H_ + tid * 4;
#pragma unroll 8
    for (int t = 0; t < 64; t++) {
        float4 v = *(const float4*)(src + (size_t)t * H_);
        s0 += v.x; s1 += v.y; s2 += v.z; s3 += v.w;
    }
    sp[tid * 4 + 0] = s0 * (1.f / 64.f);
    sp[tid * 4 + 1] = s1 * (1.f / 64.f);
    sp[tid * 4 + 2] = s2 * (1.f / 64.f);
    sp[tid * 4 + 3] = s3 * (1.f / 64.f);
    __syncthreads();
    float acc = b_h2e[tid];
    const float* wr = w_h2e + (size_t)tid * H_;
#pragma unroll 8
    for (int k = 0; k < H_; k++) acc += sp[k] * wr[k];
    g_ae[b * E_ + tid] = acc;
}

// ---------------- entry point -----------------------------------------------
extern "C" void kernel_launch(void* const* d_in, const int* in_sizes, int n_in,
                              void* d_out, int out_size) {
    const int*   x       = (const int*)d_in[0];
    const int*   lengths = (const int*)d_in[1];
    const float* emb     = (const float*)d_in[2];
    const float* w_ih    = (const float*)d_in[3];
    const float* w_hh    = (const float*)d_in[4];
    const float* b_ih    = (const float*)d_in[5];
    const float* b_hh    = (const float*)d_in[6];
    const float* wq      = (const float*)d_in[7];
    const float* bq      = (const float*)d_in[8];
    const float* wk      = (const float*)d_in[9];
    const float* bk      = (const float*)d_in[10];
    const float* wv      = (const float*)d_in[11];
    const float* bv      = (const float*)d_in[12];
    const float* wo      = (const float*)d_in[13];
    const float* bo      = (const float*)d_in[14];
    const float* w_h2e   = (const float*)d_in[15];
    const float* b_h2e   = (const float*)d_in[16];
    float* out = (float*)d_out;

    float *p_lo, *p_qkv, *p_w, *p_mho, *p_ae;
    cudaGetSymbolAddress((void**)&p_lo,   g_lstm_out);
    cudaGetSymbolAddress((void**)&p_qkv,  g_QKV);
    cudaGetSymbolAddress((void**)&p_w,    g_wout);
    cudaGetSymbolAddress((void**)&p_mho,  g_mho);
    cudaGetSymbolAddress((void**)&p_ae,   g_ae);

    static bool attr_set = false;
    if (!attr_set) {
        cudaFuncSetAttribute(lstm_persistent,
                             cudaFuncAttributeMaxDynamicSharedMemorySize,
                             LSTM_SMEM_BYTES);
        attr_set = true;
    }

    zero_init_kernel<<<(B_ * H_ + 255) / 256, 256>>>();
    bias_sum_kernel<<<(G4_ + 255) / 256, 256>>>(b_ih, b_hh);
    gather_square_kernel<<<(TB_ * E_ / 2 + 255) / 256, 256>>>(x, emb);

    // LSTM recurrence: persistent, pair-permuted LDS.64, flag barrier, e-overlap
    lstm_persistent<<<128, 256, LSTM_SMEM_BYTES>>>(w_ih, w_hh, lengths);

    // fused QKV projection -> [TB][1536]
    gemm_qkv<<<dim3(12, TB_ / 128), 256>>>(p_lo, wq, wk, wv, bq, bk, bv, p_qkv);

    attention_kernel<<<dim3(B_, NH_), 256>>>(p_qkv, lengths, p_w);

    // output projection
    gemm_tf32<false><<<dim3(H_ / 128, TB_ / 128), 256>>>(p_w, wo, bo, p_mho, TB_, H_, H_);

    // fused mean-pool + hidden_to_embedding
    pool_h2e_kernel<<<B_, 128>>>(w_h2e, b_h2e);

    // final scores = ae @ emb^T
    gemm_tf32<true><<<dim3((NITEMS + 127) / 128, B_ / 128), 256>>>(p_ae, emb, nullptr, out, B_, NITEMS, E_);
}

// round 12
// speedup vs baseline: 1.1220x; 1.1220x over previous
#include <cuda_runtime.h>
#include <math.h>
#include <stdint.h>

// Problem constants
constexpr int T_ = 64;
constexpr int B_ = 256;
constexpr int NITEMS = 100000;
constexpr int E_ = 128;
constexpr int H_ = 512;
constexpr int NH_ = 8;
constexpr int G4_ = 4 * H_;   // 2048
constexpr int TB_ = T_ * B_;  // 16384

// ---------------- scratch (device globals) ----------------------------------
__device__ float g_embs[TB_ * E_];             // tf32-rounded emb[x]^2
__device__ float g_bsum[G4_];
__device__ float g_hseq[(T_ + 1) * B_ * H_];   // tf32-rounded h per step
__device__ float g_lstm_out[TB_ * H_];         // (B,T,H), tf32-rounded
__device__ float g_QKV[TB_ * 3 * H_];          // [TB][1536]: Q|K|V
__device__ float g_poolw[B_ * H_];             // mean_t weighted (B,H)
__device__ float g_Wc[E_ * H_];                // w_h2e @ wo  (E,H)
__device__ float g_bc[E_];                     // b_h2e + w_h2e @ bo
__device__ float g_ae[B_ * E_];
__device__ unsigned int g_bar4[64];            // 4 groups, padded

// ---------------- helpers ----------------------------------------------------
__device__ __forceinline__ float tf32r(float x) {
    uint32_t u;
    asm("cvt.rna.tf32.f32 %0, %1;" : "=r"(u) : "f"(x));
    return __uint_as_float(u);
}

__device__ __forceinline__ void mma_tf32(float c[4],
                                         float a0, float a1, float a2, float a3,
                                         float b0, float b1) {
    asm volatile(
        "mma.sync.aligned.m16n8k8.row.col.f32.tf32.tf32.f32 "
        "{%0,%1,%2,%3},{%4,%5,%6,%7},{%8,%9},{%0,%1,%2,%3};"
        : "+f"(c[0]), "+f"(c[1]), "+f"(c[2]), "+f"(c[3])
        : "r"(__float_as_uint(a0)), "r"(__float_as_uint(a1)),
          "r"(__float_as_uint(a2)), "r"(__float_as_uint(a3)),
          "r"(__float_as_uint(b0)), "r"(__float_as_uint(b1)));
}

__device__ __forceinline__ float sigmoidf_(float x) {
    return 1.f / (1.f + expf(-x));
}

__device__ __forceinline__ void cp16(uint32_t d, const float* s) {
    asm volatile("cp.async.cg.shared.global [%0], [%1], 16;" :: "r"(d), "l"(s));
}
__device__ __forceinline__ void cp_commit() {
    asm volatile("cp.async.commit_group;");
}
template<int N>
__device__ __forceinline__ void cp_wait() {
    asm volatile("cp.async.wait_group %0;" :: "n"(N));
}

// ---------------- small kernels ---------------------------------------------
__global__ void zero_init_kernel() {
    int i = blockIdx.x * blockDim.x + threadIdx.x;
    if (i < B_ * H_) g_hseq[i] = 0.f;
    if (i < 64) g_bar4[i] = 0u;
}

__global__ void bias_sum_kernel(const float* __restrict__ b_ih,
                                const float* __restrict__ b_hh) {
    int i = blockIdx.x * blockDim.x + threadIdx.x;
    if (i < G4_) g_bsum[i] = b_ih[i] + b_hh[i];
}

// embs = tf32r(emb[x]^2) — pre-rounded so the LSTM can cp.async it directly.
__global__ void gather_square_kernel(const int* __restrict__ x,
                                     const float* __restrict__ emb) {
    int fi = blockIdx.x * blockDim.x + threadIdx.x;
    int row = fi >> 5;
    int c4  = fi & 31;
    int id = x[row];
    float4 v = ((const float4*)(emb + (size_t)id * E_))[c4];
    float4 o;
    o.x = tf32r(v.x * v.x); o.y = tf32r(v.y * v.y);
    o.z = tf32r(v.z * v.z); o.w = tf32r(v.w * v.w);
    ((float4*)g_embs)[fi] = o;
}

// ---------------- combined epilogue weights: Wc = w_h2e @ wo, bc -------------
// Wc[e][h] = sum_h' w_h2e[e][h'] * wo[h'][h];  bc[e] = b_h2e[e] + sum w_h2e[e][h']*bo[h']
constexpr int EPB = 4;
__global__ __launch_bounds__(256)
void combine_kernel(const float* __restrict__ wo, const float* __restrict__ bo,
                    const float* __restrict__ w_h2e, const float* __restrict__ b_h2e) {
    __shared__ float sp[EPB][H_];
    const int e0 = blockIdx.x * EPB;
    const int tid = threadIdx.x;
    const int lane = tid & 31;
    const int wid = tid >> 5;
    for (int i = tid; i < EPB * H_; i += 256)
        sp[i >> 9][i & 511] = w_h2e[(size_t)(e0 + (i >> 9)) * H_ + (i & 511)];
    __syncthreads();

    float acc[EPB][2];
#pragma unroll
    for (int i = 0; i < EPB; i++) { acc[i][0] = 0.f; acc[i][1] = 0.f; }
    for (int hp = 0; hp < H_; hp++) {
        float w0 = wo[(size_t)hp * H_ + tid];
        float w1 = wo[(size_t)hp * H_ + tid + 256];
#pragma unroll
        for (int i = 0; i < EPB; i++) {
            float s = sp[i][hp];
            acc[i][0] += s * w0;
            acc[i][1] += s * w1;
        }
    }
#pragma unroll
    for (int i = 0; i < EPB; i++) {
        g_Wc[(size_t)(e0 + i) * H_ + tid] = acc[i][0];
        g_Wc[(size_t)(e0 + i) * H_ + tid + 256] = acc[i][1];
    }
    if (wid < EPB) {
        float s = 0.f;
        for (int k = lane; k < H_; k += 32) s += sp[wid][k] * bo[k];
#pragma unroll
        for (int off = 16; off; off >>= 1) s += __shfl_down_sync(0xffffffffu, s, off);
        if (lane == 0) g_bc[e0 + wid] = b_h2e[e0 + wid] + s;
    }
}

// ae[b][e] = bc[e] + dot(poolw[b][:], Wc[e][:])
__global__ __launch_bounds__(128)
void ae_kernel() {
    __shared__ float sp[H_];
    const int b = blockIdx.x;
    const int e = threadIdx.x;
    for (int k = e; k < H_; k += 128) sp[k] = g_poolw[b * H_ + k];
    __syncthreads();
    float acc = g_bc[e];
    const float* wr = g_Wc + (size_t)e * H_;
#pragma unroll 8
    for (int k = 0; k < H_; k++) acc += sp[k] * wr[k];
    g_ae[b * E_ + e] = acc;
}

// ---------------- tf32 tensor-core GEMM: C = A(MxK) W(NxK)^T + bias ----------
template<bool CHECKN>
__global__ __launch_bounds__(256, 2)
void gemm_tf32(const float* __restrict__ A, const float* __restrict__ W,
               const float* __restrict__ bias, float* __restrict__ C,
               int M, int N, int K) {
    __shared__ __align__(16) float As[2][128][20];
    __shared__ __align__(16) float Bs[2][128][20];

    const int tid = threadIdx.x;
    const int lane = tid & 31;
    const int wid = tid >> 5;
    const int wm = (wid & 3) * 32;
    const int wn = (wid >> 2) * 64;
    const int bm = blockIdx.y * 128;
    const int bn = blockIdx.x * 128;
    const int lr = tid >> 1;
    const int lk = (tid & 1) * 8;

    int wrow = bn + lr;
    bool wok = true;
    if (CHECKN) { wok = (wrow < N); if (!wok) wrow = N - 1; }
    const float* Ap = A + (size_t)(bm + lr) * K + lk;
    const float* Wp = W + (size_t)wrow * K + lk;

    float acc[2][8][4];
#pragma unroll
    for (int mt = 0; mt < 2; mt++)
#pragma unroll
        for (int nt = 0; nt < 8; nt++)
#pragma unroll
            for (int q = 0; q < 4; q++) acc[mt][nt][q] = 0.f;

    const int gq = lane >> 2;
    const int tg = lane & 3;

    float4 pa0, pa1, pb0, pb1;
    pa0 = *(const float4*)(Ap);
    pa1 = *(const float4*)(Ap + 4);
    if (!CHECKN || wok) {
        pb0 = *(const float4*)(Wp);
        pb1 = *(const float4*)(Wp + 4);
    } else { pb0 = make_float4(0,0,0,0); pb1 = pb0; }

#define GEMM_STAGE(BUF)                                                       \
    {                                                                         \
        float4 ca0 = make_float4(tf32r(pa0.x), tf32r(pa0.y), tf32r(pa0.z), tf32r(pa0.w)); \
        float4 ca1 = make_float4(tf32r(pa1.x), tf32r(pa1.y), tf32r(pa1.z), tf32r(pa1.w)); \
        float4 cb0 = make_float4(tf32r(pb0.x), tf32r(pb0.y), tf32r(pb0.z), tf32r(pb0.w)); \
        float4 cb1 = make_float4(tf32r(pb1.x), tf32r(pb1.y), tf32r(pb1.z), tf32r(pb1.w)); \
        *(float4*)&As[BUF][lr][lk]     = ca0;                                 \
        *(float4*)&As[BUF][lr][lk + 4] = ca1;                                 \
        *(float4*)&Bs[BUF][lr][lk]     = cb0;                                 \
        *(float4*)&Bs[BUF][lr][lk + 4] = cb1;                                 \
    }

#define GEMM_COMPUTE(BUF)                                                     \
    _Pragma("unroll")                                                         \
    for (int ks = 0; ks < 16; ks += 8) {                                      \
        float a[2][4];                                                        \
        float b[8][2];                                                        \
        _Pragma("unroll")                                                     \
        for (int mt = 0; mt < 2; mt++) {                                      \
            int r = wm + mt * 16 + gq;                                        \
            int c = ks + tg;                                                  \
            a[mt][0] = As[BUF][r][c];                                         \
            a[mt][1] = As[BUF][r + 8][c];                                     \
            a[mt][2] = As[BUF][r][c + 4];                                     \
            a[mt][3] = As[BUF][r + 8][c + 4];                                 \
        }                                                                     \
        _Pragma("unroll")                                                     \
        for (int nt = 0; nt < 8; nt++) {                                      \
            int n = wn + nt * 8 + gq;                                         \
            b[nt][0] = Bs[BUF][n][ks + tg];                                   \
            b[nt][1] = Bs[BUF][n][ks + tg + 4];                               \
        }                                                                     \
        _Pragma("unroll")                                                     \
        for (int mt = 0; mt < 2; mt++)                                        \
            _Pragma("unroll")                                                 \
            for (int nt = 0; nt < 8; nt++)                                    \
                mma_tf32(acc[mt][nt], a[mt][0], a[mt][1], a[mt][2], a[mt][3], \
                         b[nt][0], b[nt][1]);                                 \
    }

    GEMM_STAGE(0)
    __syncthreads();

    int buf = 0;
    for (int k0 = 16; k0 < K; k0 += 16) {
        pa0 = *(const float4*)(Ap + k0);
        pa1 = *(const float4*)(Ap + k0 + 4);
        if (!CHECKN || wok) {
            pb0 = *(const float4*)(Wp + k0);
            pb1 = *(const float4*)(Wp + k0 + 4);
        } else { pb0 = make_float4(0,0,0,0); pb1 = pb0; }
        if (buf == 0) { GEMM_COMPUTE(0) GEMM_STAGE(1) }
        else          { GEMM_COMPUTE(1) GEMM_STAGE(0) }
        __syncthreads();
        buf ^= 1;
    }
    if (buf == 0) { GEMM_COMPUTE(0) } else { GEMM_COMPUTE(1) }

#pragma unroll
    for (int mt = 0; mt < 2; mt++) {
        int r = bm + wm + mt * 16 + gq;
#pragma unroll
        for (int nt = 0; nt < 8; nt++) {
            int cgl = bn + wn + nt * 8 + 2 * tg;
            if (CHECKN && cgl >= N) continue;
            float bv0 = 0.f, bv1 = 0.f;
            if (bias) { bv0 = bias[cgl]; bv1 = bias[cgl + 1]; }
            *(float2*)&C[(size_t)r * N + cgl] =
                make_float2(acc[mt][nt][0] + bv0, acc[mt][nt][1] + bv1);
            *(float2*)&C[(size_t)(r + 8) * N + cgl] =
                make_float2(acc[mt][nt][2] + bv0, acc[mt][nt][3] + bv1);
        }
    }
#undef GEMM_STAGE
#undef GEMM_COMPUTE
}

// ---------------- fused QKV GEMM: C[TB][1536] = A @ [wq|wk|wv]^T + bias ------
__global__ __launch_bounds__(256, 2)
void gemm_qkv(const float* __restrict__ A,
              const float* __restrict__ wq, const float* __restrict__ wk,
              const float* __restrict__ wv,
              const float* __restrict__ bq, const float* __restrict__ bk,
              const float* __restrict__ bv,
              float* __restrict__ C) {
    __shared__ __align__(16) float As[2][128][20];
    __shared__ __align__(16) float Bs[2][128][20];
    constexpr int K = H_, N = 3 * H_;

    const int tid = threadIdx.x;
    const int lane = tid & 31;
    const int wid = tid >> 5;
    const int wm = (wid & 3) * 32;
    const int wn = (wid >> 2) * 64;
    const int bm = blockIdx.y * 128;
    const int bn = blockIdx.x * 128;
    const int lr = tid >> 1;
    const int lk = (tid & 1) * 8;

    const int wrow = bn + lr;
    const int sel = wrow >> 9;
    const int wl = wrow & 511;
    const float* Wbase = (sel == 0) ? wq : ((sel == 1) ? wk : wv);
    const float* Ap = A + (size_t)(bm + lr) * K + lk;
    const float* Wp = Wbase + (size_t)wl * K + lk;

    float acc[2][8][4];
#pragma unroll
    for (int mt = 0; mt < 2; mt++)
#pragma unroll
        for (int nt = 0; nt < 8; nt++)
#pragma unroll
            for (int q = 0; q < 4; q++) acc[mt][nt][q] = 0.f;

    const int gq = lane >> 2;
    const int tg = lane & 3;

    float4 pa0, pa1, pb0, pb1;
    pa0 = *(const float4*)(Ap);
    pa1 = *(const float4*)(Ap + 4);
    pb0 = *(const float4*)(Wp);
    pb1 = *(const float4*)(Wp + 4);

#define QKV_STAGE(BUF)                                                        \
    {                                                                         \
        float4 ca0 = make_float4(tf32r(pa0.x), tf32r(pa0.y), tf32r(pa0.z), tf32r(pa0.w)); \
        float4 ca1 = make_float4(tf32r(pa1.x), tf32r(pa1.y), tf32r(pa1.z), tf32r(pa1.w)); \
        float4 cb0 = make_float4(tf32r(pb0.x), tf32r(pb0.y), tf32r(pb0.z), tf32r(pb0.w)); \
        float4 cb1 = make_float4(tf32r(pb1.x), tf32r(pb1.y), tf32r(pb1.z), tf32r(pb1.w)); \
        *(float4*)&As[BUF][lr][lk]     = ca0;                                 \
        *(float4*)&As[BUF][lr][lk + 4] = ca1;                                 \
        *(float4*)&Bs[BUF][lr][lk]     = cb0;                                 \
        *(float4*)&Bs[BUF][lr][lk + 4] = cb1;                                 \
    }

#define QKV_COMPUTE(BUF)                                                      \
    _Pragma("unroll")                                                         \
    for (int ks = 0; ks < 16; ks += 8) {                                      \
        float a[2][4];                                                        \
        float b[8][2];                                                        \
        _Pragma("unroll")                                                     \
        for (int mt = 0; mt < 2; mt++) {                                      \
            int r = wm + mt * 16 + gq;                                        \
            int c = ks + tg;                                                  \
            a[mt][0] = As[BUF][r][c];                                         \
            a[mt][1] = As[BUF][r + 8][c];                                     \
            a[mt][2] = As[BUF][r][c + 4];                                     \
            a[mt][3] = As[BUF][r + 8][c + 4];                                 \
        }                                                                     \
        _Pragma("unroll")                                                     \
        for (int nt = 0; nt < 8; nt++) {                                      \
            int n = wn + nt * 8 + gq;                                         \
            b[nt][0] = Bs[BUF][n][ks + tg];                                   \
            b[nt][1] = Bs[BUF][n][ks + tg + 4];                               \
        }                                                                     \
        _Pragma("unroll")                                                     \
        for (int mt = 0; mt < 2; mt++)                                        \
            _Pragma("unroll")                                                 \
            for (int nt = 0; nt < 8; nt++)                                    \
                mma_tf32(acc[mt][nt], a[mt][0], a[mt][1], a[mt][2], a[mt][3], \
                         b[nt][0], b[nt][1]);                                 \
    }

    QKV_STAGE(0)
    __syncthreads();

    int buf = 0;
    for (int k0 = 16; k0 < K; k0 += 16) {
        pa0 = *(const float4*)(Ap + k0);
        pa1 = *(const float4*)(Ap + k0 + 4);
        pb0 = *(const float4*)(Wp + k0);
        pb1 = *(const float4*)(Wp + k0 + 4);
        if (buf == 0) { QKV_COMPUTE(0) QKV_STAGE(1) }
        else          { QKV_COMPUTE(1) QKV_STAGE(0) }
        __syncthreads();
        buf ^= 1;
    }
    if (buf == 0) { QKV_COMPUTE(0) } else { QKV_COMPUTE(1) }

#pragma unroll
    for (int mt = 0; mt < 2; mt++) {
        int r = bm + wm + mt * 16 + gq;
#pragma unroll
        for (int nt = 0; nt < 8; nt++) {
            int cgl = bn + wn + nt * 8 + 2 * tg;
            int selc = cgl >> 9;
            int lc = cgl & 511;
            const float* bb = (selc == 0) ? bq : ((selc == 1) ? bk : bv);
            float bv0 = bb[lc], bv1 = bb[lc + 1];
            *(float2*)&C[(size_t)r * N + cgl] =
                make_float2(acc[mt][nt][0] + bv0, acc[mt][nt][1] + bv1);
            *(float2*)&C[(size_t)(r + 8) * N + cgl] =
                make_float2(acc[mt][nt][2] + bv0, acc[mt][nt][3] + bv1);
        }
    }
#undef QKV_STAGE
#undef QKV_COMPUTE
}

// ---------------- persistent tensor-core LSTM (R9 design, proven 738us) -----
constexpr int WHH_STR = 516;
constexpr int WIH_STR = 132;
constexpr int HS_STR  = 68;
constexpr int WHH_FLOATS = 64 * WHH_STR;
constexpr int WIH_FLOATS = 64 * WIH_STR;
constexpr int STG_FLOATS = 64 * HS_STR;
constexpr int LSTM_SMEM_BYTES = (WHH_FLOATS + WIH_FLOATS + 3 * STG_FLOATS) * 4;

__device__ __forceinline__ void lstm_comp(const float* HS, const float* WS,
                                          int wstr, int coff,
                                          int wm, int wn, int gq, int tg,
                                          float (&acc)[2][2][4]) {
#pragma unroll
    for (int ks = 0; ks < 64; ks += 8) {
        float a[2][4];
        float bf[2][2];
#pragma unroll
        for (int mt = 0; mt < 2; mt++) {
            int r = wm + mt * 16 + gq;
            int cc = ks + tg;
            a[mt][0] = HS[r * HS_STR + cc];
            a[mt][1] = HS[(r + 8) * HS_STR + cc];
            a[mt][2] = HS[r * HS_STR + cc + 4];
            a[mt][3] = HS[(r + 8) * HS_STR + cc + 4];
        }
#pragma unroll
        for (int nt = 0; nt < 2; nt++) {
            int n = wn + nt * 8 + gq;
            bf[nt][0] = WS[n * wstr + coff + ks + tg];
            bf[nt][1] = WS[n * wstr + coff + ks + tg + 4];
        }
#pragma unroll
        for (int mt = 0; mt < 2; mt++)
#pragma unroll
            for (int nt = 0; nt < 2; nt++)
                mma_tf32(acc[mt][nt], a[mt][0], a[mt][1], a[mt][2], a[mt][3],
                         bf[nt][0], bf[nt][1]);
    }
}

__global__ __launch_bounds__(256, 1)
void lstm_persistent(const float* __restrict__ w_ih,    // (4H,E)
                     const float* __restrict__ w_hh,    // (4H,H)
                     const int* __restrict__ lengths) {
    extern __shared__ __align__(16) float dsm[];
    float* ws_hh = dsm;
    float* ws_ih = ws_hh + WHH_FLOATS;
    float* stage = ws_ih + WIH_FLOATS;         // 3 buffers of STG_FLOATS
    float* ps    = stage + 1 * STG_FLOATS;     // alias buffer 1

    const int tid = threadIdx.x;
    const int lane = tid & 31;
    const int wid = tid >> 5;
    const int wm = (wid & 1) * 32;
    const int wn = (wid >> 1) * 16;
    const int j0 = (blockIdx.x & 31) * 16;
    const int b0 = (blockIdx.x >> 5) * 64;
    const int grp = blockIdx.x >> 5;

    const int gq = lane >> 2;
    const int tg = lane & 3;

    for (int idx = tid; idx < 64 * 128; idx += 256) {
        int n = idx >> 7;
        int k4 = (idx & 127) * 4;
        int g = n >> 4, jl = n & 15;
        float4 v = *(const float4*)(w_hh + (size_t)(g * H_ + j0 + jl) * H_ + k4);
        float* dst = ws_hh + n * WHH_STR + k4;
        dst[0] = tf32r(v.x); dst[1] = tf32r(v.y);
        dst[2] = tf32r(v.z); dst[3] = tf32r(v.w);
    }
    for (int idx = tid; idx < 64 * 32; idx += 256) {
        int n = idx >> 5;
        int k4 = (idx & 31) * 4;
        int g = n >> 4, jl = n & 15;
        float4 v = *(const float4*)(w_ih + (size_t)(g * H_ + j0 + jl) * E_ + k4);
        float* dst = ws_ih + n * WIH_STR + k4;
        dst[0] = tf32r(v.x); dst[1] = tf32r(v.y);
        dst[2] = tf32r(v.z); dst[3] = tf32r(v.w);
    }
    __syncthreads();

    const int row = tid >> 2;
    const int cg = tid & 3;
    const float* e_base = g_embs + (size_t)(b0 + row) * E_ + cg * 16;
    const float* h_base = g_hseq + (size_t)(b0 + row) * H_ + cg * 16;

    uint32_t stage_u32 = (uint32_t)__cvta_generic_to_shared(stage);
    uint32_t stg_u32[3];
#pragma unroll
    for (int bff = 0; bff < 3; bff++)
        stg_u32[bff] = stage_u32 + (uint32_t)(bff * STG_FLOATS + row * HS_STR + cg * 16) * 4u;

    int lenp[4];
    float bi[4], bfo[4], bg[4], bo4[4];
    float creg[4];
#pragma unroll
    for (int p = 0; p < 4; p++) {
        int idx = tid + p * 256;
        int jloc = idx & 15;
        int bl = idx >> 4;
        lenp[p] = lengths[b0 + bl];
        int j = j0 + jloc;
        bi[p]  = g_bsum[j];
        bfo[p] = g_bsum[H_ + j];
        bg[p]  = g_bsum[2 * H_ + j];
        bo4[p] = g_bsum[3 * H_ + j];
        creg[p] = 0.f;
    }

    for (int t = 0; t < T_; t++) {
        const float* e_t = e_base + (size_t)t * B_ * E_;
        const float* h_t = h_base + (size_t)t * B_ * H_;

        auto issue = [&](int c, uint32_t dst) {
            const float* s = (c < 2) ? (e_t + c * 64) : (h_t + (c - 2) * 64);
            cp16(dst, s); cp16(dst + 16, s + 4);
            cp16(dst + 32, s + 8); cp16(dst + 48, s + 12);
            cp_commit();
        };

        float acc[2][2][4];
#pragma unroll
        for (int mt = 0; mt < 2; mt++)
#pragma unroll
            for (int nt = 0; nt < 2; nt++)
#pragma unroll
                for (int q = 0; q < 4; q++) acc[mt][nt][q] = 0.f;

        issue(0, stg_u32[0]);
        issue(1, stg_u32[1]);

#pragma unroll
        for (int c = 0; c < 10; c++) {
            if (c < 9) cp_wait<1>(); else cp_wait<0>();
            __syncthreads();
            if (c + 2 < 10) issue(c + 2, stg_u32[(c + 2) % 3]);
            const float* HS = stage + (c % 3) * STG_FLOATS;
            if (c < 2)
                lstm_comp(HS, ws_ih, WIH_STR, c * 64, wm, wn, gq, tg, acc);
            else
                lstm_comp(HS, ws_hh, WHH_STR, (c - 2) * 64, wm, wn, gq, tg, acc);
        }

        __syncthreads();
#pragma unroll
        for (int mt = 0; mt < 2; mt++) {
            int r = wm + mt * 16 + gq;
#pragma unroll
            for (int nt = 0; nt < 2; nt++) {
                int c = wn + nt * 8 + 2 * tg;
                *(float2*)&ps[r * HS_STR + c] = make_float2(acc[mt][nt][0], acc[mt][nt][1]);
                *(float2*)&ps[(r + 8) * HS_STR + c] = make_float2(acc[mt][nt][2], acc[mt][nt][3]);
            }
        }
        __syncthreads();

        float* hout = g_hseq + (size_t)(t + 1) * B_ * H_;
#pragma unroll
        for (int p = 0; p < 4; p++) {
            int idx = tid + p * 256;
            int jloc = idx & 15;
            int bl = idx >> 4;
            int b = b0 + bl;
            int j = j0 + jloc;
            float gi = sigmoidf_(ps[bl * HS_STR + jloc]      + bi[p]);
            float gf = sigmoidf_(ps[bl * HS_STR + 16 + jloc] + bfo[p]);
            float gg = tanhf(    ps[bl * HS_STR + 32 + jloc] + bg[p]);
            float go = sigmoidf_(ps[bl * HS_STR + 48 + jloc] + bo4[p]);
            float cn = gf * creg[p] + gi * gg;
            creg[p] = cn;
            float hn = tf32r(go * tanhf(cn));
            hout[(size_t)b * H_ + j] = hn;
            g_lstm_out[(size_t)(b * T_ + t) * H_ + j] = (t < lenp[p]) ? hn : 0.f;
        }
        __syncthreads();

        if (t != T_ - 1) {
            if (tid == 0) {
                __threadfence();
                atomicAdd(&g_bar4[grp * 16], 1u);
                unsigned target = 32u * (unsigned)(t + 1);
                volatile unsigned* vb = &g_bar4[grp * 16];
                while (*vb < target) __nanosleep(32);
            }
            __syncthreads();
        }
    }
}

// ---------------- attention + in-block t-pooling -----------------------------
// One block per (b, head). Writes its disjoint 64-col slice of poolw directly.
__global__ __launch_bounds__(256)
void attention_kernel(const float* __restrict__ QKV,
                      const int* __restrict__ lengths,
                      float* __restrict__ poolw) {
    __shared__ float qs[64 * 64];
    __shared__ float ks[64 * 64];
    __shared__ float ss[64 * 64];
    const int b = blockIdx.x, nh = blockIdx.y;
    const int tid = threadIdx.x;
    const int len = lengths[b];
    const size_t qkvbase = ((size_t)b * 64) * 1536 + nh * 64;

#pragma unroll
    for (int l = 0; l < 4; l++) {
        int fidx = tid + (l << 8);
        int r = fidx & 63, c4 = fidx >> 6;
        float4 qv = *(const float4*)(QKV + qkvbase + (size_t)r * 1536 + c4 * 4);
        float4 kv = *(const float4*)(QKV + qkvbase + 512 + (size_t)r * 1536 + c4 * 4);
        qs[(c4 * 4 + 0) * 64 + r] = qv.x; qs[(c4 * 4 + 1) * 64 + r] = qv.y;
        qs[(c4 * 4 + 2) * 64 + r] = qv.z; qs[(c4 * 4 + 3) * 64 + r] = qv.w;
        ks[(c4 * 4 + 0) * 64 + r] = kv.x; ks[(c4 * 4 + 1) * 64 + r] = kv.y;
        ks[(c4 * 4 + 2) * 64 + r] = kv.z; ks[(c4 * 4 + 3) * 64 + r] = kv.w;
    }
    __syncthreads();

    const int tx = tid & 15, ty = tid >> 4;
    const int r0 = ty * 4, c0 = tx * 4;
    float acc[4][4];
#pragma unroll
    for (int i = 0; i < 4; i++)
#pragma unroll
        for (int j = 0; j < 4; j++) acc[i][j] = 0.f;

#pragma unroll 8
    for (int k = 0; k < 64; k++) {
        float4 aq = *(const float4*)&qs[k * 64 + r0];
        float4 bk = *(const float4*)&ks[k * 64 + c0];
        float a[4] = {aq.x, aq.y, aq.z, aq.w};
        float bb[4] = {bk.x, bk.y, bk.z, bk.w};
#pragma unroll
        for (int i = 0; i < 4; i++)
#pragma unroll
            for (int j = 0; j < 4; j++) acc[i][j] += a[i] * bb[j];
    }
#pragma unroll
    for (int i = 0; i < 4; i++)
#pragma unroll
        for (int j = 0; j < 4; j++) {
            int c = c0 + j;
            ss[(r0 + i) * 64 + c] = (c < len) ? acc[i][j] * 0.125f : -1e30f;
        }
    __syncthreads();

    float* vs = qs;
#pragma unroll
    for (int l = 0; l < 4; l++) {
        int fidx = tid + (l << 8);
        int r = fidx >> 4, c4 = fidx & 15;
        ((float4*)vs)[fidx] =
            *(const float4*)(QKV + qkvbase + 1024 + (size_t)r * 1536 + c4 * 4);
    }
    if (tid < 64) {
        float m = -1e30f;
#pragma unroll 8
        for (int c = 0; c < 64; c++) m = fmaxf(m, ss[tid * 64 + c]);
        float s = 0.f;
#pragma unroll 8
        for (int c = 0; c < 64; c++) {
            float e = expf(ss[tid * 64 + c] - m);
            ss[tid * 64 + c] = e;
            s += e;
        }
        float inv = 1.f / s;
#pragma unroll 8
        for (int c = 0; c < 64; c++) ss[tid * 64 + c] *= inv;
    }
    __syncthreads();

    float o[4][4];
#pragma unroll
    for (int i = 0; i < 4; i++)
#pragma unroll
        for (int j = 0; j < 4; j++) o[i][j] = 0.f;
#pragma unroll 8
    for (int k = 0; k < 64; k++) {
        float a[4];
#pragma unroll
        for (int i = 0; i < 4; i++) a[i] = ss[(r0 + i) * 64 + k];
        float4 vv4 = *(const float4*)&vs[k * 64 + c0];
        float vv[4] = {vv4.x, vv4.y, vv4.z, vv4.w};
#pragma unroll
        for (int i = 0; i < 4; i++)
#pragma unroll
            for (int j = 0; j < 4; j++) o[i][j] += a[i] * vv[j];
    }

    // pool over t (all 64 rows): reduce within block, write poolw slice
    __syncthreads();   // done reading ss/vs
#pragma unroll
    for (int j = 0; j < 4; j++)
        ss[ty * 64 + c0 + j] = o[0][j] + o[1][j] + o[2][j] + o[3][j];
    __syncthreads();
    if (tid < 64) {
        float s = 0.f;
#pragma unroll
        for (int g = 0; g < 16; g++) s += ss[g * 64 + tid];
        poolw[(size_t)b * H_ + nh * 64 + tid] = s * (1.f / 64.f);
    }
}

// ---------------- entry point -----------------------------------------------
extern "C" void kernel_launch(void* const* d_in, const int* in_sizes, int n_in,
                              void* d_out, int out_size) {
    const int*   x       = (const int*)d_in[0];
    const int*   lengths = (const int*)d_in[1];
    const float* emb     = (const float*)d_in[2];
    const float* w_ih    = (const float*)d_in[3];
    const float* w_hh    = (const float*)d_in[4];
    const float* b_ih    = (const float*)d_in[5];
    const float* b_hh    = (const float*)d_in[6];
    const float* wq      = (const float*)d_in[7];
    const float* bq      = (const float*)d_in[8];
    const float* wk      = (const float*)d_in[9];
    const float* bk      = (const float*)d_in[10];
    const float* wv      = (const float*)d_in[11];
    const float* bv      = (const float*)d_in[12];
    const float* wo      = (const float*)d_in[13];
    const float* bo      = (const float*)d_in[14];
    const float* w_h2e   = (const float*)d_in[15];
    const float* b_h2e   = (const float*)d_in[16];
    float* out = (float*)d_out;

    float *p_lo, *p_qkv, *p_pool, *p_ae;
    cudaGetSymbolAddress((void**)&p_lo,   g_lstm_out);
    cudaGetSymbolAddress((void**)&p_qkv,  g_QKV);
    cudaGetSymbolAddress((void**)&p_pool, g_poolw);
    cudaGetSymbolAddress((void**)&p_ae,   g_ae);

    static bool attr_set = false;
    if (!attr_set) {
        cudaFuncSetAttribute(lstm_persistent,
                             cudaFuncAttributeMaxDynamicSharedMemorySize,
                             LSTM_SMEM_BYTES);
        attr_set = true;
    }

    zero_init_kernel<<<(B_ * H_ + 255) / 256, 256>>>();
    bias_sum_kernel<<<(G4_ + 255) / 256, 256>>>(b_ih, b_hh);
    gather_square_kernel<<<(TB_ * E_ / 4 + 255) / 256, 256>>>(x, emb);
    combine_kernel<<<E_ / EPB, 256>>>(wo, bo, w_h2e, b_h2e);

    // LSTM recurrence (R9 persistent design)
    lstm_persistent<<<128, 256, LSTM_SMEM_BYTES>>>(w_ih, w_hh, lengths);

    // fused QKV projection -> [TB][1536]
    gemm_qkv<<<dim3(12, TB_ / 128), 256>>>(p_lo, wq, wk, wv, bq, bk, bv, p_qkv);

    // attention + in-block mean-pool over t -> poolw (B,H)
    attention_kernel<<<dim3(B_, NH_), 256>>>(p_qkv, lengths, p_pool);

    // ae = poolw @ Wc^T + bc  (combined O-proj + h2e)
    ae_kernel<<<B_, 128>>>();

    // final scores = ae @ emb^T
    gemm_tf32<true><<<dim3((NITEMS + 127) / 128, B_ / 128), 256>>>(p_ae, emb, nullptr, out, B_, NITEMS, E_);
}

// round 13
// speedup vs baseline: 1.1746x; 1.0469x over previous
#include <cuda_runtime.h>
#include <math.h>
#include <stdint.h>

// Problem constants
constexpr int T_ = 64;
constexpr int B_ = 256;
constexpr int NITEMS = 100000;
constexpr int E_ = 128;
constexpr int H_ = 512;
constexpr int NH_ = 8;
constexpr int G4_ = 4 * H_;   // 2048
constexpr int TB_ = T_ * B_;  // 16384

// ---------------- scratch (device globals) ----------------------------------
__device__ float g_embs[TB_ * E_];             // tf32-rounded emb[x]^2
__device__ float g_bsum[G4_];
__device__ float g_hseq[(T_ + 1) * B_ * H_];   // tf32-rounded h per step
__device__ float g_lstm_out[TB_ * H_];         // (B,T,H), tf32-rounded
__device__ float g_QKV[TB_ * 3 * H_];          // [TB][1536]: Q|K|V
__device__ float g_poolw[B_ * H_];             // mean_t weighted (B,H)
__device__ float g_Wc[E_ * H_];                // w_h2e @ wo  (E,H)
__device__ float g_bc[E_];                     // b_h2e + w_h2e @ bo
__device__ float g_ae[B_ * E_];
__device__ unsigned int g_bar4[64];            // 4 groups, padded

// ---------------- helpers ----------------------------------------------------
__device__ __forceinline__ float tf32r(float x) {
    uint32_t u;
    asm("cvt.rna.tf32.f32 %0, %1;" : "=r"(u) : "f"(x));
    return __uint_as_float(u);
}

__device__ __forceinline__ void mma_tf32(float c[4],
                                         float a0, float a1, float a2, float a3,
                                         float b0, float b1) {
    asm volatile(
        "mma.sync.aligned.m16n8k8.row.col.f32.tf32.tf32.f32 "
        "{%0,%1,%2,%3},{%4,%5,%6,%7},{%8,%9},{%0,%1,%2,%3};"
        : "+f"(c[0]), "+f"(c[1]), "+f"(c[2]), "+f"(c[3])
        : "r"(__float_as_uint(a0)), "r"(__float_as_uint(a1)),
          "r"(__float_as_uint(a2)), "r"(__float_as_uint(a3)),
          "r"(__float_as_uint(b0)), "r"(__float_as_uint(b1)));
}

__device__ __forceinline__ float sigmoidf_(float x) {
    return 1.f / (1.f + expf(-x));
}

__device__ __forceinline__ void cp16(uint32_t d, const float* s) {
    asm volatile("cp.async.cg.shared.global [%0], [%1], 16;" :: "r"(d), "l"(s));
}
__device__ __forceinline__ void cp_commit() {
    asm volatile("cp.async.commit_group;");
}
template<int N>
__device__ __forceinline__ void cp_wait() {
    asm volatile("cp.async.wait_group %0;" :: "n"(N));
}

// ---------------- small kernels ---------------------------------------------
__global__ void zero_init_kernel() {
    int i = blockIdx.x * blockDim.x + threadIdx.x;
    if (i < B_ * H_) g_hseq[i] = 0.f;
    if (i < 64) g_bar4[i] = 0u;
}

__global__ void bias_sum_kernel(const float* __restrict__ b_ih,
                                const float* __restrict__ b_hh) {
    int i = blockIdx.x * blockDim.x + threadIdx.x;
    if (i < G4_) g_bsum[i] = b_ih[i] + b_hh[i];
}

// embs = tf32r(emb[x]^2) — pre-rounded so the LSTM can cp.async it directly.
__global__ void gather_square_kernel(const int* __restrict__ x,
                                     const float* __restrict__ emb) {
    int fi = blockIdx.x * blockDim.x + threadIdx.x;
    int row = fi >> 5;
    int c4  = fi & 31;
    int id = x[row];
    float4 v = ((const float4*)(emb + (size_t)id * E_))[c4];
    float4 o;
    o.x = tf32r(v.x * v.x); o.y = tf32r(v.y * v.y);
    o.z = tf32r(v.z * v.z); o.w = tf32r(v.w * v.w);
    ((float4*)g_embs)[fi] = o;
}

// ---------------- combined epilogue weights v2: Wc = w_h2e @ wo, bc ----------
// grid (32, 4): e0 = bx*4 rows, h0 = by*128 cols. 256 thr: col=tid&127, K split
// in halves across tid>>7, reduced via smem. 128 blocks -> chip-wide parallel.
constexpr int EPB = 4;
__global__ __launch_bounds__(256)
void combine_kernel(const float* __restrict__ wo, const float* __restrict__ bo,
                    const float* __restrict__ w_h2e, const float* __restrict__ b_h2e) {
    __shared__ float sp[EPB][H_];      // w_h2e rows (8 KB)
    __shared__ float part[EPB][128];   // K-half partials (2 KB)
    const int e0 = blockIdx.x * EPB;
    const int h0 = blockIdx.y * 128;
    const int tid = threadIdx.x;
    const int col = tid & 127;
    const int kh = tid >> 7;           // 0 or 1

    for (int i = tid; i < EPB * H_; i += 256)
        sp[i >> 9][i & 511] = w_h2e[(size_t)(e0 + (i >> 9)) * H_ + (i & 511)];
    __syncthreads();

    float acc[EPB] = {0.f, 0.f, 0.f, 0.f};
    const int hp0 = kh * 256;
#pragma unroll 4
    for (int hp = hp0; hp < hp0 + 256; hp++) {
        float wv = wo[(size_t)hp * H_ + h0 + col];
#pragma unroll
        for (int i = 0; i < EPB; i++) acc[i] += sp[i][hp] * wv;
    }
    if (kh == 1) {
#pragma unroll
        for (int i = 0; i < EPB; i++) part[i][col] = acc[i];
    }
    __syncthreads();
    if (kh == 0) {
#pragma unroll
        for (int i = 0; i < EPB; i++)
            g_Wc[(size_t)(e0 + i) * H_ + h0 + col] = acc[i] + part[i][col];
    }

    // bias (once per e-block)
    if (blockIdx.y == 0) {
        const int lane = tid & 31, wid = tid >> 5;
        if (wid < EPB) {
            float s = 0.f;
            for (int k = lane; k < H_; k += 32) s += sp[wid][k] * bo[k];
#pragma unroll
            for (int off = 16; off; off >>= 1) s += __shfl_down_sync(0xffffffffu, s, off);
            if (lane == 0) g_bc[e0 + wid] = b_h2e[e0 + wid] + s;
        }
    }
}

// ae[b][e] = bc[e] + dot(poolw[b][:], Wc[e][:])
__global__ __launch_bounds__(128)
void ae_kernel() {
    __shared__ float sp[H_];
    const int b = blockIdx.x;
    const int e = threadIdx.x;
    for (int k = e; k < H_; k += 128) sp[k] = g_poolw[b * H_ + k];
    __syncthreads();
    float acc = g_bc[e];
    const float* wr = g_Wc + (size_t)e * H_;
#pragma unroll 8
    for (int k = 0; k < H_; k++) acc += sp[k] * wr[k];
    g_ae[b * E_ + e] = acc;
}

// ---------------- tf32 tensor-core GEMM: C = A(MxK) W(NxK)^T + bias ----------
template<bool CHECKN>
__global__ __launch_bounds__(256, 2)
void gemm_tf32(const float* __restrict__ A, const float* __restrict__ W,
               const float* __restrict__ bias, float* __restrict__ C,
               int M, int N, int K) {
    __shared__ __align__(16) float As[2][128][20];
    __shared__ __align__(16) float Bs[2][128][20];

    const int tid = threadIdx.x;
    const int lane = tid & 31;
    const int wid = tid >> 5;
    const int wm = (wid & 3) * 32;
    const int wn = (wid >> 2) * 64;
    const int bm = blockIdx.y * 128;
    const int bn = blockIdx.x * 128;
    const int lr = tid >> 1;
    const int lk = (tid & 1) * 8;

    int wrow = bn + lr;
    bool wok = true;
    if (CHECKN) { wok = (wrow < N); if (!wok) wrow = N - 1; }
    const float* Ap = A + (size_t)(bm + lr) * K + lk;
    const float* Wp = W + (size_t)wrow * K + lk;

    float acc[2][8][4];
#pragma unroll
    for (int mt = 0; mt < 2; mt++)
#pragma unroll
        for (int nt = 0; nt < 8; nt++)
#pragma unroll
            for (int q = 0; q < 4; q++) acc[mt][nt][q] = 0.f;

    const int gq = lane >> 2;
    const int tg = lane & 3;

    float4 pa0, pa1, pb0, pb1;
    pa0 = *(const float4*)(Ap);
    pa1 = *(const float4*)(Ap + 4);
    if (!CHECKN || wok) {
        pb0 = *(const float4*)(Wp);
        pb1 = *(const float4*)(Wp + 4);
    } else { pb0 = make_float4(0,0,0,0); pb1 = pb0; }

#define GEMM_STAGE(BUF)                                                       \
    {                                                                         \
        float4 ca0 = make_float4(tf32r(pa0.x), tf32r(pa0.y), tf32r(pa0.z), tf32r(pa0.w)); \
        float4 ca1 = make_float4(tf32r(pa1.x), tf32r(pa1.y), tf32r(pa1.z), tf32r(pa1.w)); \
        float4 cb0 = make_float4(tf32r(pb0.x), tf32r(pb0.y), tf32r(pb0.z), tf32r(pb0.w)); \
        float4 cb1 = make_float4(tf32r(pb1.x), tf32r(pb1.y), tf32r(pb1.z), tf32r(pb1.w)); \
        *(float4*)&As[BUF][lr][lk]     = ca0;                                 \
        *(float4*)&As[BUF][lr][lk + 4] = ca1;                                 \
        *(float4*)&Bs[BUF][lr][lk]     = cb0;                                 \
        *(float4*)&Bs[BUF][lr][lk + 4] = cb1;                                 \
    }

#define GEMM_COMPUTE(BUF)                                                     \
    _Pragma("unroll")                                                         \
    for (int ks = 0; ks < 16; ks += 8) {                                      \
        float a[2][4];                                                        \
        float b[8][2];                                                        \
        _Pragma("unroll")                                                     \
        for (int mt = 0; mt < 2; mt++) {                                      \
            int r = wm + mt * 16 + gq;                                        \
            int c = ks + tg;                                                  \
            a[mt][0] = As[BUF][r][c];                                         \
            a[mt][1] = As[BUF][r + 8][c];                                     \
            a[mt][2] = As[BUF][r][c + 4];                                     \
            a[mt][3] = As[BUF][r + 8][c + 4];                                 \
        }                                                                     \
        _Pragma("unroll")                                                     \
        for (int nt = 0; nt < 8; nt++) {                                      \
            int n = wn + nt * 8 + gq;                                         \
            b[nt][0] = Bs[BUF][n][ks + tg];                                   \
            b[nt][1] = Bs[BUF][n][ks + tg + 4];                               \
        }                                                                     \
        _Pragma("unroll")                                                     \
        for (int mt = 0; mt < 2; mt++)                                        \
            _Pragma("unroll")                                                 \
            for (int nt = 0; nt < 8; nt++)                                    \
                mma_tf32(acc[mt][nt], a[mt][0], a[mt][1], a[mt][2], a[mt][3], \
                         b[nt][0], b[nt][1]);                                 \
    }

    GEMM_STAGE(0)
    __syncthreads();

    int buf = 0;
    for (int k0 = 16; k0 < K; k0 += 16) {
        pa0 = *(const float4*)(Ap + k0);
        pa1 = *(const float4*)(Ap + k0 + 4);
        if (!CHECKN || wok) {
            pb0 = *(const float4*)(Wp + k0);
            pb1 = *(const float4*)(Wp + k0 + 4);
        } else { pb0 = make_float4(0,0,0,0); pb1 = pb0; }
        if (buf == 0) { GEMM_COMPUTE(0) GEMM_STAGE(1) }
        else          { GEMM_COMPUTE(1) GEMM_STAGE(0) }
        __syncthreads();
        buf ^= 1;
    }
    if (buf == 0) { GEMM_COMPUTE(0) } else { GEMM_COMPUTE(1) }

#pragma unroll
    for (int mt = 0; mt < 2; mt++) {
        int r = bm + wm + mt * 16 + gq;
#pragma unroll
        for (int nt = 0; nt < 8; nt++) {
            int cgl = bn + wn + nt * 8 + 2 * tg;
            if (CHECKN && cgl >= N) continue;
            float bv0 = 0.f, bv1 = 0.f;
            if (bias) { bv0 = bias[cgl]; bv1 = bias[cgl + 1]; }
            *(float2*)&C[(size_t)r * N + cgl] =
                make_float2(acc[mt][nt][0] + bv0, acc[mt][nt][1] + bv1);
            *(float2*)&C[(size_t)(r + 8) * N + cgl] =
                make_float2(acc[mt][nt][2] + bv0, acc[mt][nt][3] + bv1);
        }
    }
#undef GEMM_STAGE
#undef GEMM_COMPUTE
}

// ---------------- fused QKV GEMM: C[TB][1536] = A @ [wq|wk|wv]^T + bias ------
__global__ __launch_bounds__(256, 2)
void gemm_qkv(const float* __restrict__ A,
              const float* __restrict__ wq, const float* __restrict__ wk,
              const float* __restrict__ wv,
              const float* __restrict__ bq, const float* __restrict__ bk,
              const float* __restrict__ bv,
              float* __restrict__ C) {
    __shared__ __align__(16) float As[2][128][20];
    __shared__ __align__(16) float Bs[2][128][20];
    constexpr int K = H_, N = 3 * H_;

    const int tid = threadIdx.x;
    const int lane = tid & 31;
    const int wid = tid >> 5;
    const int wm = (wid & 3) * 32;
    const int wn = (wid >> 2) * 64;
    const int bm = blockIdx.y * 128;
    const int bn = blockIdx.x * 128;
    const int lr = tid >> 1;
    const int lk = (tid & 1) * 8;

    const int wrow = bn + lr;
    const int sel = wrow >> 9;
    const int wl = wrow & 511;
    const float* Wbase = (sel == 0) ? wq : ((sel == 1) ? wk : wv);
    const float* Ap = A + (size_t)(bm + lr) * K + lk;
    const float* Wp = Wbase + (size_t)wl * K + lk;

    float acc[2][8][4];
#pragma unroll
    for (int mt = 0; mt < 2; mt++)
#pragma unroll
        for (int nt = 0; nt < 8; nt++)
#pragma unroll
            for (int q = 0; q < 4; q++) acc[mt][nt][q] = 0.f;

    const int gq = lane >> 2;
    const int tg = lane & 3;

    float4 pa0, pa1, pb0, pb1;
    pa0 = *(const float4*)(Ap);
    pa1 = *(const float4*)(Ap + 4);
    pb0 = *(const float4*)(Wp);
    pb1 = *(const float4*)(Wp + 4);

#define QKV_STAGE(BUF)                                                        \
    {                                                                         \
        float4 ca0 = make_float4(tf32r(pa0.x), tf32r(pa0.y), tf32r(pa0.z), tf32r(pa0.w)); \
        float4 ca1 = make_float4(tf32r(pa1.x), tf32r(pa1.y), tf32r(pa1.z), tf32r(pa1.w)); \
        float4 cb0 = make_float4(tf32r(pb0.x), tf32r(pb0.y), tf32r(pb0.z), tf32r(pb0.w)); \
        float4 cb1 = make_float4(tf32r(pb1.x), tf32r(pb1.y), tf32r(pb1.z), tf32r(pb1.w)); \
        *(float4*)&As[BUF][lr][lk]     = ca0;                                 \
        *(float4*)&As[BUF][lr][lk + 4] = ca1;                                 \
        *(float4*)&Bs[BUF][lr][lk]     = cb0;                                 \
        *(float4*)&Bs[BUF][lr][lk + 4] = cb1;                                 \
    }

#define QKV_COMPUTE(BUF)                                                      \
    _Pragma("unroll")                                                         \
    for (int ks = 0; ks < 16; ks += 8) {                                      \
        float a[2][4];                                                        \
        float b[8][2];                                                        \
        _Pragma("unroll")                                                     \
        for (int mt = 0; mt < 2; mt++) {                                      \
            int r = wm + mt * 16 + gq;                                        \
            int c = ks + tg;                                                  \
            a[mt][0] = As[BUF][r][c];                                         \
            a[mt][1] = As[BUF][r + 8][c];                                     \
            a[mt][2] = As[BUF][r][c + 4];                                     \
            a[mt][3] = As[BUF][r + 8][c + 4];                                 \
        }                                                                     \
        _Pragma("unroll")                                                     \
        for (int nt = 0; nt < 8; nt++) {                                      \
            int n = wn + nt * 8 + gq;                                         \
            b[nt][0] = Bs[BUF][n][ks + tg];                                   \
            b[nt][1] = Bs[BUF][n][ks + tg + 4];                               \
        }                                                                     \
        _Pragma("unroll")                                                     \
        for (int mt = 0; mt < 2; mt++)                                        \
            _Pragma("unroll")                                                 \
            for (int nt = 0; nt < 8; nt++)                                    \
                mma_tf32(acc[mt][nt], a[mt][0], a[mt][1], a[mt][2], a[mt][3], \
                         b[nt][0], b[nt][1]);                                 \
    }

    QKV_STAGE(0)
    __syncthreads();

    int buf = 0;
    for (int k0 = 16; k0 < K; k0 += 16) {
        pa0 = *(const float4*)(Ap + k0);
        pa1 = *(const float4*)(Ap + k0 + 4);
        pb0 = *(const float4*)(Wp + k0);
        pb1 = *(const float4*)(Wp + k0 + 4);
        if (buf == 0) { QKV_COMPUTE(0) QKV_STAGE(1) }
        else          { QKV_COMPUTE(1) QKV_STAGE(0) }
        __syncthreads();
        buf ^= 1;
    }
    if (buf == 0) { QKV_COMPUTE(0) } else { QKV_COMPUTE(1) }

#pragma unroll
    for (int mt = 0; mt < 2; mt++) {
        int r = bm + wm + mt * 16 + gq;
#pragma unroll
        for (int nt = 0; nt < 8; nt++) {
            int cgl = bn + wn + nt * 8 + 2 * tg;
            int selc = cgl >> 9;
            int lc = cgl & 511;
            const float* bb = (selc == 0) ? bq : ((selc == 1) ? bk : bv);
            float bv0 = bb[lc], bv1 = bb[lc + 1];
            *(float2*)&C[(size_t)r * N + cgl] =
                make_float2(acc[mt][nt][0] + bv0, acc[mt][nt][1] + bv1);
            *(float2*)&C[(size_t)(r + 8) * N + cgl] =
                make_float2(acc[mt][nt][2] + bv0, acc[mt][nt][3] + bv1);
        }
    }
#undef QKV_STAGE
#undef QKV_COMPUTE
}

// ---------------- persistent tensor-core LSTM (R9 design, proven 738us) -----
constexpr int WHH_STR = 516;
constexpr int WIH_STR = 132;
constexpr int HS_STR  = 68;
constexpr int WHH_FLOATS = 64 * WHH_STR;
constexpr int WIH_FLOATS = 64 * WIH_STR;
constexpr int STG_FLOATS = 64 * HS_STR;
constexpr int LSTM_SMEM_BYTES = (WHH_FLOATS + WIH_FLOATS + 3 * STG_FLOATS) * 4;

__device__ __forceinline__ void lstm_comp(const float* HS, const float* WS,
                                          int wstr, int coff,
                                          int wm, int wn, int gq, int tg,
                                          float (&acc)[2][2][4]) {
#pragma unroll
    for (int ks = 0; ks < 64; ks += 8) {
        float a[2][4];
        float bf[2][2];
#pragma unroll
        for (int mt = 0; mt < 2; mt++) {
            int r = wm + mt * 16 + gq;
            int cc = ks + tg;
            a[mt][0] = HS[r * HS_STR + cc];
            a[mt][1] = HS[(r + 8) * HS_STR + cc];
            a[mt][2] = HS[r * HS_STR + cc + 4];
            a[mt][3] = HS[(r + 8) * HS_STR + cc + 4];
        }
#pragma unroll
        for (int nt = 0; nt < 2; nt++) {
            int n = wn + nt * 8 + gq;
            bf[nt][0] = WS[n * wstr + coff + ks + tg];
            bf[nt][1] = WS[n * wstr + coff + ks + tg + 4];
        }
#pragma unroll
        for (int mt = 0; mt < 2; mt++)
#pragma unroll
            for (int nt = 0; nt < 2; nt++)
                mma_tf32(acc[mt][nt], a[mt][0], a[mt][1], a[mt][2], a[mt][3],
                         bf[nt][0], bf[nt][1]);
    }
}

__global__ __launch_bounds__(256, 1)
void lstm_persistent(const float* __restrict__ w_ih,    // (4H,E)
                     const float* __restrict__ w_hh,    // (4H,H)
                     const int* __restrict__ lengths) {
    extern __shared__ __align__(16) float dsm[];
    float* ws_hh = dsm;
    float* ws_ih = ws_hh + WHH_FLOATS;
    float* stage = ws_ih + WIH_FLOATS;         // 3 buffers of STG_FLOATS
    float* ps    = stage + 1 * STG_FLOATS;     // alias buffer 1

    const int tid = threadIdx.x;
    const int lane = tid & 31;
    const int wid = tid >> 5;
    const int wm = (wid & 1) * 32;
    const int wn = (wid >> 1) * 16;
    const int j0 = (blockIdx.x & 31) * 16;
    const int b0 = (blockIdx.x >> 5) * 64;
    const int grp = blockIdx.x >> 5;

    const int gq = lane >> 2;
    const int tg = lane & 3;

    for (int idx = tid; idx < 64 * 128; idx += 256) {
        int n = idx >> 7;
        int k4 = (idx & 127) * 4;
        int g = n >> 4, jl = n & 15;
        float4 v = *(const float4*)(w_hh + (size_t)(g * H_ + j0 + jl) * H_ + k4);
        float* dst = ws_hh + n * WHH_STR + k4;
        dst[0] = tf32r(v.x); dst[1] = tf32r(v.y);
        dst[2] = tf32r(v.z); dst[3] = tf32r(v.w);
    }
    for (int idx = tid; idx < 64 * 32; idx += 256) {
        int n = idx >> 5;
        int k4 = (idx & 31) * 4;
        int g = n >> 4, jl = n & 15;
        float4 v = *(const float4*)(w_ih + (size_t)(g * H_ + j0 + jl) * E_ + k4);
        float* dst = ws_ih + n * WIH_STR + k4;
        dst[0] = tf32r(v.x); dst[1] = tf32r(v.y);
        dst[2] = tf32r(v.z); dst[3] = tf32r(v.w);
    }
    __syncthreads();

    const int row = tid >> 2;
    const int cg = tid & 3;
    const float* e_base = g_embs + (size_t)(b0 + row) * E_ + cg * 16;
    const float* h_base = g_hseq + (size_t)(b0 + row) * H_ + cg * 16;

    uint32_t stage_u32 = (uint32_t)__cvta_generic_to_shared(stage);
    uint32_t stg_u32[3];
#pragma unroll
    for (int bff = 0; bff < 3; bff++)
        stg_u32[bff] = stage_u32 + (uint32_t)(bff * STG_FLOATS + row * HS_STR + cg * 16) * 4u;

    int lenp[4];
    float bi[4], bfo[4], bg[4], bo4[4];
    float creg[4];
#pragma unroll
    for (int p = 0; p < 4; p++) {
        int idx = tid + p * 256;
        int jloc = idx & 15;
        int bl = idx >> 4;
        lenp[p] = lengths[b0 + bl];
        int j = j0 + jloc;
        bi[p]  = g_bsum[j];
        bfo[p] = g_bsum[H_ + j];
        bg[p]  = g_bsum[2 * H_ + j];
        bo4[p] = g_bsum[3 * H_ + j];
        creg[p] = 0.f;
    }

    for (int t = 0; t < T_; t++) {
        const float* e_t = e_base + (size_t)t * B_ * E_;
        const float* h_t = h_base + (size_t)t * B_ * H_;

        auto issue = [&](int c, uint32_t dst) {
            const float* s = (c < 2) ? (e_t + c * 64) : (h_t + (c - 2) * 64);
            cp16(dst, s); cp16(dst + 16, s + 4);
            cp16(dst + 32, s + 8); cp16(dst + 48, s + 12);
            cp_commit();
        };

        float acc[2][2][4];
#pragma unroll
        for (int mt = 0; mt < 2; mt++)
#pragma unroll
            for (int nt = 0; nt < 2; nt++)
#pragma unroll
                for (int q = 0; q < 4; q++) acc[mt][nt][q] = 0.f;

        issue(0, stg_u32[0]);
        issue(1, stg_u32[1]);

#pragma unroll
        for (int c = 0; c < 10; c++) {
            if (c < 9) cp_wait<1>(); else cp_wait<0>();
            __syncthreads();
            if (c + 2 < 10) issue(c + 2, stg_u32[(c + 2) % 3]);
            const float* HS = stage + (c % 3) * STG_FLOATS;
            if (c < 2)
                lstm_comp(HS, ws_ih, WIH_STR, c * 64, wm, wn, gq, tg, acc);
            else
                lstm_comp(HS, ws_hh, WHH_STR, (c - 2) * 64, wm, wn, gq, tg, acc);
        }

        __syncthreads();
#pragma unroll
        for (int mt = 0; mt < 2; mt++) {
            int r = wm + mt * 16 + gq;
#pragma unroll
            for (int nt = 0; nt < 2; nt++) {
                int c = wn + nt * 8 + 2 * tg;
                *(float2*)&ps[r * HS_STR + c] = make_float2(acc[mt][nt][0], acc[mt][nt][1]);
                *(float2*)&ps[(r + 8) * HS_STR + c] = make_float2(acc[mt][nt][2], acc[mt][nt][3]);
            }
        }
        __syncthreads();

        float* hout = g_hseq + (size_t)(t + 1) * B_ * H_;
#pragma unroll
        for (int p = 0; p < 4; p++) {
            int idx = tid + p * 256;
            int jloc = idx & 15;
            int bl = idx >> 4;
            int b = b0 + bl;
            int j = j0 + jloc;
            float gi = sigmoidf_(ps[bl * HS_STR + jloc]      + bi[p]);
            float gf = sigmoidf_(ps[bl * HS_STR + 16 + jloc] + bfo[p]);
            float gg = tanhf(    ps[bl * HS_STR + 32 + jloc] + bg[p]);
            float go = sigmoidf_(ps[bl * HS_STR + 48 + jloc] + bo4[p]);
            float cn = gf * creg[p] + gi * gg;
            creg[p] = cn;
            float hn = tf32r(go * tanhf(cn));
            hout[(size_t)b * H_ + j] = hn;
            g_lstm_out[(size_t)(b * T_ + t) * H_ + j] = (t < lenp[p]) ? hn : 0.f;
        }
        __syncthreads();

        if (t != T_ - 1) {
            if (tid == 0) {
                __threadfence();
                atomicAdd(&g_bar4[grp * 16], 1u);
                unsigned target = 32u * (unsigned)(t + 1);
                volatile unsigned* vb = &g_bar4[grp * 16];
                while (*vb < target) __nanosleep(32);
            }
            __syncthreads();
        }
    }
}

// ---------------- attention + in-block t-pooling -----------------------------
__global__ __launch_bounds__(256)
void attention_kernel(const float* __restrict__ QKV,
                      const int* __restrict__ lengths,
                      float* __restrict__ poolw) {
    __shared__ float qs[64 * 64];
    __shared__ float ks[64 * 64];
    __shared__ float ss[64 * 64];
    const int b = blockIdx.x, nh = blockIdx.y;
    const int tid = threadIdx.x;
    const int len = lengths[b];
    const size_t qkvbase = ((size_t)b * 64) * 1536 + nh * 64;

#pragma unroll
    for (int l = 0; l < 4; l++) {
        int fidx = tid + (l << 8);
        int r = fidx & 63, c4 = fidx >> 6;
        float4 qv = *(const float4*)(QKV + qkvbase + (size_t)r * 1536 + c4 * 4);
        float4 kv = *(const float4*)(QKV + qkvbase + 512 + (size_t)r * 1536 + c4 * 4);
        qs[(c4 * 4 + 0) * 64 + r] = qv.x; qs[(c4 * 4 + 1) * 64 + r] = qv.y;
        qs[(c4 * 4 + 2) * 64 + r] = qv.z; qs[(c4 * 4 + 3) * 64 + r] = qv.w;
        ks[(c4 * 4 + 0) * 64 + r] = kv.x; ks[(c4 * 4 + 1) * 64 + r] = kv.y;
        ks[(c4 * 4 + 2) * 64 + r] = kv.z; ks[(c4 * 4 + 3) * 64 + r] = kv.w;
    }
    __syncthreads();

    const int tx = tid & 15, ty = tid >> 4;
    const int r0 = ty * 4, c0 = tx * 4;
    float acc[4][4];
#pragma unroll
    for (int i = 0; i < 4; i++)
#pragma unroll
        for (int j = 0; j < 4; j++) acc[i][j] = 0.f;

#pragma unroll 8
    for (int k = 0; k < 64; k++) {
        float4 aq = *(const float4*)&qs[k * 64 + r0];
        float4 bk = *(const float4*)&ks[k * 64 + c0];
        float a[4] = {aq.x, aq.y, aq.z, aq.w};
        float bb[4] = {bk.x, bk.y, bk.z, bk.w};
#pragma unroll
        for (int i = 0; i < 4; i++)
#pragma unroll
            for (int j = 0; j < 4; j++) acc[i][j] += a[i] * bb[j];
    }
#pragma unroll
    for (int i = 0; i < 4; i++)
#pragma unroll
        for (int j = 0; j < 4; j++) {
            int c = c0 + j;
            ss[(r0 + i) * 64 + c] = (c < len) ? acc[i][j] * 0.125f : -1e30f;
        }
    __syncthreads();

    float* vs = qs;
#pragma unroll
    for (int l = 0; l < 4; l++) {
        int fidx = tid + (l << 8);
        int r = fidx >> 4, c4 = fidx & 15;
        ((float4*)vs)[fidx] =
            *(const float4*)(QKV + qkvbase + 1024 + (size_t)r * 1536 + c4 * 4);
    }
    if (tid < 64) {
        float m = -1e30f;
#pragma unroll 8
        for (int c = 0; c < 64; c++) m = fmaxf(m, ss[tid * 64 + c]);
        float s = 0.f;
#pragma unroll 8
        for (int c = 0; c < 64; c++) {
            float e = expf(ss[tid * 64 + c] - m);
            ss[tid * 64 + c] = e;
            s += e;
        }
        float inv = 1.f / s;
#pragma unroll 8
        for (int c = 0; c < 64; c++) ss[tid * 64 + c] *= inv;
    }
    __syncthreads();

    float o[4][4];
#pragma unroll
    for (int i = 0; i < 4; i++)
#pragma unroll
        for (int j = 0; j < 4; j++) o[i][j] = 0.f;
#pragma unroll 8
    for (int k = 0; k < 64; k++) {
        float a[4];
#pragma unroll
        for (int i = 0; i < 4; i++) a[i] = ss[(r0 + i) * 64 + k];
        float4 vv4 = *(const float4*)&vs[k * 64 + c0];
        float vv[4] = {vv4.x, vv4.y, vv4.z, vv4.w};
#pragma unroll
        for (int i = 0; i < 4; i++)
#pragma unroll
            for (int j = 0; j < 4; j++) o[i][j] += a[i] * vv[j];
    }

    // pool over t (all 64 rows): reduce within block, write poolw slice
    __syncthreads();   // done reading ss/vs
#pragma unroll
    for (int j = 0; j < 4; j++)
        ss[ty * 64 + c0 + j] = o[0][j] + o[1][j] + o[2][j] + o[3][j];
    __syncthreads();
    if (tid < 64) {
        float s = 0.f;
#pragma unroll
        for (int g = 0; g < 16; g++) s += ss[g * 64 + tid];
        poolw[(size_t)b * H_ + nh * 64 + tid] = s * (1.f / 64.f);
    }
}

// ---------------- entry point -----------------------------------------------
extern "C" void kernel_launch(void* const* d_in, const int* in_sizes, int n_in,
                              void* d_out, int out_size) {
    const int*   x       = (const int*)d_in[0];
    const int*   lengths = (const int*)d_in[1];
    const float* emb     = (const float*)d_in[2];
    const float* w_ih    = (const float*)d_in[3];
    const float* w_hh    = (const float*)d_in[4];
    const float* b_ih    = (const float*)d_in[5];
    const float* b_hh    = (const float*)d_in[6];
    const float* wq      = (const float*)d_in[7];
    const float* bq      = (const float*)d_in[8];
    const float* wk      = (const float*)d_in[9];
    const float* bk      = (const float*)d_in[10];
    const float* wv      = (const float*)d_in[11];
    const float* bv      = (const float*)d_in[12];
    const float* wo      = (const float*)d_in[13];
    const float* bo      = (const float*)d_in[14];
    const float* w_h2e   = (const float*)d_in[15];
    const float* b_h2e   = (const float*)d_in[16];
    float* out = (float*)d_out;

    float *p_lo, *p_qkv, *p_pool, *p_ae;
    cudaGetSymbolAddress((void**)&p_lo,   g_lstm_out);
    cudaGetSymbolAddress((void**)&p_qkv,  g_QKV);
    cudaGetSymbolAddress((void**)&p_pool, g_poolw);
    cudaGetSymbolAddress((void**)&p_ae,   g_ae);

    static bool attr_set = false;
    if (!attr_set) {
        cudaFuncSetAttribute(lstm_persistent,
                             cudaFuncAttributeMaxDynamicSharedMemorySize,
                             LSTM_SMEM_BYTES);
        attr_set = true;
    }

    zero_init_kernel<<<(B_ * H_ + 255) / 256, 256>>>();
    bias_sum_kernel<<<(G4_ + 255) / 256, 256>>>(b_ih, b_hh);
    gather_square_kernel<<<(TB_ * E_ / 4 + 255) / 256, 256>>>(x, emb);
    combine_kernel<<<dim3(E_ / EPB, 4), 256>>>(wo, bo, w_h2e, b_h2e);

    // LSTM recurrence (R9 persistent design)
    lstm_persistent<<<128, 256, LSTM_SMEM_BYTES>>>(w_ih, w_hh, lengths);

    // fused QKV projection -> [TB][1536]
    gemm_qkv<<<dim3(12, TB_ / 128), 256>>>(p_lo, wq, wk, wv, bq, bk, bv, p_qkv);

    // attention + in-block mean-pool over t -> poolw (B,H)
    attention_kernel<<<dim3(B_, NH_), 256>>>(p_qkv, lengths, p_pool);

    // ae = poolw @ Wc^T + bc  (combined O-proj + h2e)
    ae_kernel<<<B_, 128>>>();

    // final scores = ae @ emb^T
    gemm_tf32<true><<<dim3((NITEMS + 127) / 128, B_ / 128), 256>>>(p_ae, emb, nullptr, out, B_, NITEMS, E_);
}

// round 14
// speedup vs baseline: 1.2351x; 1.0516x over previous
#include <cuda_runtime.h>
#include <math.h>
#include <stdint.h>

// Problem constants
constexpr int T_ = 64;
constexpr int B_ = 256;
constexpr int NITEMS = 100000;
constexpr int E_ = 128;
constexpr int H_ = 512;
constexpr int NH_ = 8;
constexpr int G4_ = 4 * H_;   // 2048
constexpr int TB_ = T_ * B_;  // 16384

// ---------------- scratch (device globals) ----------------------------------
__device__ float g_embs[TB_ * E_];             // tf32-rounded emb[x]^2
__device__ float g_bsum[G4_];
__device__ float g_hseq[(T_ + 1) * B_ * H_];   // tf32-rounded h per step
__device__ float g_lstm_out[TB_ * H_];         // (B,T,H), tf32-rounded
__device__ float g_QKV[TB_ * 3 * H_];          // [TB][1536]: Q|K|V
__device__ float g_poolw[B_ * H_];             // mean_t weighted (B,H)
__device__ float g_Wc[E_ * H_];                // w_h2e @ wo  (E,H)
__device__ float g_bc[E_];                     // b_h2e + w_h2e @ bo
__device__ float g_ae[B_ * E_];
__device__ unsigned int g_bar4[64];            // 4 groups, padded

// ---------------- helpers ----------------------------------------------------
__device__ __forceinline__ float tf32r(float x) {
    uint32_t u;
    asm("cvt.rna.tf32.f32 %0, %1;" : "=r"(u) : "f"(x));
    return __uint_as_float(u);
}

__device__ __forceinline__ void mma_tf32(float c[4],
                                         float a0, float a1, float a2, float a3,
                                         float b0, float b1) {
    asm volatile(
        "mma.sync.aligned.m16n8k8.row.col.f32.tf32.tf32.f32 "
        "{%0,%1,%2,%3},{%4,%5,%6,%7},{%8,%9},{%0,%1,%2,%3};"
        : "+f"(c[0]), "+f"(c[1]), "+f"(c[2]), "+f"(c[3])
        : "r"(__float_as_uint(a0)), "r"(__float_as_uint(a1)),
          "r"(__float_as_uint(a2)), "r"(__float_as_uint(a3)),
          "r"(__float_as_uint(b0)), "r"(__float_as_uint(b1)));
}

// fast sigmoid / tanh via MUFU (__expf err ~2ulp on bounded inputs; clamp for safety)
__device__ __forceinline__ float sigmoid_fast(float x) {
    x = fminf(fmaxf(x, -30.f), 30.f);
    float t = __expf(-x);
    return __fdividef(1.f, 1.f + t);
}
__device__ __forceinline__ float tanh_fast(float x) {
    x = fminf(fmaxf(x, -15.f), 15.f);
    float t = __expf(2.f * x);
    return __fdividef(t - 1.f, t + 1.f);
}

__device__ __forceinline__ void cp16(uint32_t d, const float* s) {
    asm volatile("cp.async.cg.shared.global [%0], [%1], 16;" :: "r"(d), "l"(s));
}
__device__ __forceinline__ void cp_commit() {
    asm volatile("cp.async.commit_group;");
}
template<int N>
__device__ __forceinline__ void cp_wait() {
    asm volatile("cp.async.wait_group %0;" :: "n"(N));
}

// ---------------- small kernels ---------------------------------------------
__global__ void zero_init_kernel() {
    int i = blockIdx.x * blockDim.x + threadIdx.x;
    if (i < B_ * H_) g_hseq[i] = 0.f;
    if (i < 64) g_bar4[i] = 0u;
}

__global__ void bias_sum_kernel(const float* __restrict__ b_ih,
                                const float* __restrict__ b_hh) {
    int i = blockIdx.x * blockDim.x + threadIdx.x;
    if (i < G4_) g_bsum[i] = b_ih[i] + b_hh[i];
}

__global__ void gather_square_kernel(const int* __restrict__ x,
                                     const float* __restrict__ emb) {
    int fi = blockIdx.x * blockDim.x + threadIdx.x;
    int row = fi >> 5;
    int c4  = fi & 31;
    int id = x[row];
    float4 v = ((const float4*)(emb + (size_t)id * E_))[c4];
    float4 o;
    o.x = tf32r(v.x * v.x); o.y = tf32r(v.y * v.y);
    o.z = tf32r(v.z * v.z); o.w = tf32r(v.w * v.w);
    ((float4*)g_embs)[fi] = o;
}

// ---------------- combined epilogue weights v3 -------------------------------
// grid (32, 16): e0=bx*4, h0=by*32. Block 256: col=tid&31, kq=tid>>5 (8 K-slices
// of 64). 64-iter serial chains; smem tree reduce. 512 blocks chip-wide.
constexpr int EPB = 4;
__global__ __launch_bounds__(256)
void combine_kernel(const float* __restrict__ wo, const float* __restrict__ bo,
                    const float* __restrict__ w_h2e, const float* __restrict__ b_h2e) {
    __shared__ float sp[EPB][H_];        // w_h2e rows (8 KB)
    __shared__ float part[8][EPB][32];   // per-kq partials (4 KB)
    const int e0 = blockIdx.x * EPB;
    const int h0 = blockIdx.y * 32;
    const int tid = threadIdx.x;
    const int col = tid & 31;
    const int kq = tid >> 5;            // 0..7

    for (int i = tid; i < EPB * H_; i += 256)
        sp[i >> 9][i & 511] = w_h2e[(size_t)(e0 + (i >> 9)) * H_ + (i & 511)];
    __syncthreads();

    float acc[EPB] = {0.f, 0.f, 0.f, 0.f};
    const int hp0 = kq * 64;
#pragma unroll 8
    for (int hp = hp0; hp < hp0 + 64; hp++) {
        float wv = wo[(size_t)hp * H_ + h0 + col];
#pragma unroll
        for (int i = 0; i < EPB; i++) acc[i] += sp[i][hp] * wv;
    }
#pragma unroll
    for (int i = 0; i < EPB; i++) part[kq][i][col] = acc[i];
    __syncthreads();
    if (kq < EPB) {   // warp kq handles e-row kq
        float s = part[0][kq][col];
#pragma unroll
        for (int q = 1; q < 8; q++) s += part[q][kq][col];
        g_Wc[(size_t)(e0 + kq) * H_ + h0 + col] = s;
    }

    // bias (once per e-block)
    if (blockIdx.y == 0) {
        const int lane = tid & 31, wid = tid >> 5;
        if (wid < EPB) {
            float s = 0.f;
            for (int k = lane; k < H_; k += 32) s += sp[wid][k] * bo[k];
#pragma unroll
            for (int off = 16; off; off >>= 1) s += __shfl_down_sync(0xffffffffu, s, off);
            if (lane == 0) g_bc[e0 + wid] = b_h2e[e0 + wid] + s;
        }
    }
}

// ae[b][e] = bc[e] + dot(poolw[b][:], Wc[e][:])
__global__ __launch_bounds__(128)
void ae_kernel() {
    __shared__ float sp[H_];
    const int b = blockIdx.x;
    const int e = threadIdx.x;
    for (int k = e; k < H_; k += 128) sp[k] = g_poolw[b * H_ + k];
    __syncthreads();
    float acc = g_bc[e];
    const float* wr = g_Wc + (size_t)e * H_;
#pragma unroll 8
    for (int k = 0; k < H_; k++) acc += sp[k] * wr[k];
    g_ae[b * E_ + e] = acc;
}

// ---------------- tf32 tensor-core GEMM: C = A(MxK) W(NxK)^T + bias ----------
template<bool CHECKN>
__global__ __launch_bounds__(256, 2)
void gemm_tf32(const float* __restrict__ A, const float* __restrict__ W,
               const float* __restrict__ bias, float* __restrict__ C,
               int M, int N, int K) {
    __shared__ __align__(16) float As[2][128][20];
    __shared__ __align__(16) float Bs[2][128][20];

    const int tid = threadIdx.x;
    const int lane = tid & 31;
    const int wid = tid >> 5;
    const int wm = (wid & 3) * 32;
    const int wn = (wid >> 2) * 64;
    const int bm = blockIdx.y * 128;
    const int bn = blockIdx.x * 128;
    const int lr = tid >> 1;
    const int lk = (tid & 1) * 8;

    int wrow = bn + lr;
    bool wok = true;
    if (CHECKN) { wok = (wrow < N); if (!wok) wrow = N - 1; }
    const float* Ap = A + (size_t)(bm + lr) * K + lk;
    const float* Wp = W + (size_t)wrow * K + lk;

    float acc[2][8][4];
#pragma unroll
    for (int mt = 0; mt < 2; mt++)
#pragma unroll
        for (int nt = 0; nt < 8; nt++)
#pragma unroll
            for (int q = 0; q < 4; q++) acc[mt][nt][q] = 0.f;

    const int gq = lane >> 2;
    const int tg = lane & 3;

    float4 pa0, pa1, pb0, pb1;
    pa0 = *(const float4*)(Ap);
    pa1 = *(const float4*)(Ap + 4);
    if (!CHECKN || wok) {
        pb0 = *(const float4*)(Wp);
        pb1 = *(const float4*)(Wp + 4);
    } else { pb0 = make_float4(0,0,0,0); pb1 = pb0; }

#define GEMM_STAGE(BUF)                                                       \
    {                                                                         \
        float4 ca0 = make_float4(tf32r(pa0.x), tf32r(pa0.y), tf32r(pa0.z), tf32r(pa0.w)); \
        float4 ca1 = make_float4(tf32r(pa1.x), tf32r(pa1.y), tf32r(pa1.z), tf32r(pa1.w)); \
        float4 cb0 = make_float4(tf32r(pb0.x), tf32r(pb0.y), tf32r(pb0.z), tf32r(pb0.w)); \
        float4 cb1 = make_float4(tf32r(pb1.x), tf32r(pb1.y), tf32r(pb1.z), tf32r(pb1.w)); \
        *(float4*)&As[BUF][lr][lk]     = ca0;                                 \
        *(float4*)&As[BUF][lr][lk + 4] = ca1;                                 \
        *(float4*)&Bs[BUF][lr][lk]     = cb0;                                 \
        *(float4*)&Bs[BUF][lr][lk + 4] = cb1;                                 \
    }

#define GEMM_COMPUTE(BUF)                                                     \
    _Pragma("unroll")                                                         \
    for (int ks = 0; ks < 16; ks += 8) {                                      \
        float a[2][4];                                                        \
        float b[8][2];                                                        \
        _Pragma("unroll")                                                     \
        for (int mt = 0; mt < 2; mt++) {                                      \
            int r = wm + mt * 16 + gq;                                        \
            int c = ks + tg;                                                  \
            a[mt][0] = As[BUF][r][c];                                         \
            a[mt][1] = As[BUF][r + 8][c];                                     \
            a[mt][2] = As[BUF][r][c + 4];                                     \
            a[mt][3] = As[BUF][r + 8][c + 4];                                 \
        }                                                                     \
        _Pragma("unroll")                                                     \
        for (int nt = 0; nt < 8; nt++) {                                      \
            int n = wn + nt * 8 + gq;                                         \
            b[nt][0] = Bs[BUF][n][ks + tg];                                   \
            b[nt][1] = Bs[BUF][n][ks + tg + 4];                               \
        }                                                                     \
        _Pragma("unroll")                                                     \
        for (int mt = 0; mt < 2; mt++)                                        \
            _Pragma("unroll")                                                 \
            for (int nt = 0; nt < 8; nt++)                                    \
                mma_tf32(acc[mt][nt], a[mt][0], a[mt][1], a[mt][2], a[mt][3], \
                         b[nt][0], b[nt][1]);                                 \
    }

    GEMM_STAGE(0)
    __syncthreads();

    int buf = 0;
    for (int k0 = 16; k0 < K; k0 += 16) {
        pa0 = *(const float4*)(Ap + k0);
        pa1 = *(const float4*)(Ap + k0 + 4);
        if (!CHECKN || wok) {
            pb0 = *(const float4*)(Wp + k0);
            pb1 = *(const float4*)(Wp + k0 + 4);
        } else { pb0 = make_float4(0,0,0,0); pb1 = pb0; }
        if (buf == 0) { GEMM_COMPUTE(0) GEMM_STAGE(1) }
        else          { GEMM_COMPUTE(1) GEMM_STAGE(0) }
        __syncthreads();
        buf ^= 1;
    }
    if (buf == 0) { GEMM_COMPUTE(0) } else { GEMM_COMPUTE(1) }

#pragma unroll
    for (int mt = 0; mt < 2; mt++) {
        int r = bm + wm + mt * 16 + gq;
#pragma unroll
        for (int nt = 0; nt < 8; nt++) {
            int cgl = bn + wn + nt * 8 + 2 * tg;
            if (CHECKN && cgl >= N) continue;
            float bv0 = 0.f, bv1 = 0.f;
            if (bias) { bv0 = bias[cgl]; bv1 = bias[cgl + 1]; }
            *(float2*)&C[(size_t)r * N + cgl] =
                make_float2(acc[mt][nt][0] + bv0, acc[mt][nt][1] + bv1);
            *(float2*)&C[(size_t)(r + 8) * N + cgl] =
                make_float2(acc[mt][nt][2] + bv0, acc[mt][nt][3] + bv1);
        }
    }
#undef GEMM_STAGE
#undef GEMM_COMPUTE
}

// ---------------- fused QKV GEMM: C[TB][1536] = A @ [wq|wk|wv]^T + bias ------
__global__ __launch_bounds__(256, 2)
void gemm_qkv(const float* __restrict__ A,
              const float* __restrict__ wq, const float* __restrict__ wk,
              const float* __restrict__ wv,
              const float* __restrict__ bq, const float* __restrict__ bk,
              const float* __restrict__ bv,
              float* __restrict__ C) {
    __shared__ __align__(16) float As[2][128][20];
    __shared__ __align__(16) float Bs[2][128][20];
    constexpr int K = H_, N = 3 * H_;

    const int tid = threadIdx.x;
    const int lane = tid & 31;
    const int wid = tid >> 5;
    const int wm = (wid & 3) * 32;
    const int wn = (wid >> 2) * 64;
    const int bm = blockIdx.y * 128;
    const int bn = blockIdx.x * 128;
    const int lr = tid >> 1;
    const int lk = (tid & 1) * 8;

    const int wrow = bn + lr;
    const int sel = wrow >> 9;
    const int wl = wrow & 511;
    const float* Wbase = (sel == 0) ? wq : ((sel == 1) ? wk : wv);
    const float* Ap = A + (size_t)(bm + lr) * K + lk;
    const float* Wp = Wbase + (size_t)wl * K + lk;

    float acc[2][8][4];
#pragma unroll
    for (int mt = 0; mt < 2; mt++)
#pragma unroll
        for (int nt = 0; nt < 8; nt++)
#pragma unroll
            for (int q = 0; q < 4; q++) acc[mt][nt][q] = 0.f;

    const int gq = lane >> 2;
    const int tg = lane & 3;

    float4 pa0, pa1, pb0, pb1;
    pa0 = *(const float4*)(Ap);
    pa1 = *(const float4*)(Ap + 4);
    pb0 = *(const float4*)(Wp);
    pb1 = *(const float4*)(Wp + 4);

#define QKV_STAGE(BUF)                                                        \
    {                                                                         \
        float4 ca0 = make_float4(tf32r(pa0.x), tf32r(pa0.y), tf32r(pa0.z), tf32r(pa0.w)); \
        float4 ca1 = make_float4(tf32r(pa1.x), tf32r(pa1.y), tf32r(pa1.z), tf32r(pa1.w)); \
        float4 cb0 = make_float4(tf32r(pb0.x), tf32r(pb0.y), tf32r(pb0.z), tf32r(pb0.w)); \
        float4 cb1 = make_float4(tf32r(pb1.x), tf32r(pb1.y), tf32r(pb1.z), tf32r(pb1.w)); \
        *(float4*)&As[BUF][lr][lk]     = ca0;                                 \
        *(float4*)&As[BUF][lr][lk + 4] = ca1;                                 \
        *(float4*)&Bs[BUF][lr][lk]     = cb0;                                 \
        *(float4*)&Bs[BUF][lr][lk + 4] = cb1;                                 \
    }

#define QKV_COMPUTE(BUF)                                                      \
    _Pragma("unroll")                                                         \
    for (int ks = 0; ks < 16; ks += 8) {                                      \
        float a[2][4];                                                        \
        float b[8][2];                                                        \
        _Pragma("unroll")                                                     \
        for (int mt = 0; mt < 2; mt++) {                                      \
            int r = wm + mt * 16 + gq;                                        \
            int c = ks + tg;                                                  \
            a[mt][0] = As[BUF][r][c];                                         \
            a[mt][1] = As[BUF][r + 8][c];                                     \
            a[mt][2] = As[BUF][r][c + 4];                                     \
            a[mt][3] = As[BUF][r + 8][c + 4];                                 \
        }                                                                     \
        _Pragma("unroll")                                                     \
        for (int nt = 0; nt < 8; nt++) {                                      \
            int n = wn + nt * 8 + gq;                                         \
            b[nt][0] = Bs[BUF][n][ks + tg];                                   \
            b[nt][1] = Bs[BUF][n][ks + tg + 4];                               \
        }                                                                     \
        _Pragma("unroll")                                                     \
        for (int mt = 0; mt < 2; mt++)                                        \
            _Pragma("unroll")                                                 \
            for (int nt = 0; nt < 8; nt++)                                    \
                mma_tf32(acc[mt][nt], a[mt][0], a[mt][1], a[mt][2], a[mt][3], \
                         b[nt][0], b[nt][1]);                                 \
    }

    QKV_STAGE(0)
    __syncthreads();

    int buf = 0;
    for (int k0 = 16; k0 < K; k0 += 16) {
        pa0 = *(const float4*)(Ap + k0);
        pa1 = *(const float4*)(Ap + k0 + 4);
        pb0 = *(const float4*)(Wp + k0);
        pb1 = *(const float4*)(Wp + k0 + 4);
        if (buf == 0) { QKV_COMPUTE(0) QKV_STAGE(1) }
        else          { QKV_COMPUTE(1) QKV_STAGE(0) }
        __syncthreads();
        buf ^= 1;
    }
    if (buf == 0) { QKV_COMPUTE(0) } else { QKV_COMPUTE(1) }

#pragma unroll
    for (int mt = 0; mt < 2; mt++) {
        int r = bm + wm + mt * 16 + gq;
#pragma unroll
        for (int nt = 0; nt < 8; nt++) {
            int cgl = bn + wn + nt * 8 + 2 * tg;
            int selc = cgl >> 9;
            int lc = cgl & 511;
            const float* bb = (selc == 0) ? bq : ((selc == 1) ? bk : bv);
            float bv0 = bb[lc], bv1 = bb[lc + 1];
            *(float2*)&C[(size_t)r * N + cgl] =
                make_float2(acc[mt][nt][0] + bv0, acc[mt][nt][1] + bv1);
            *(float2*)&C[(size_t)(r + 8) * N + cgl] =
                make_float2(acc[mt][nt][2] + bv0, acc[mt][nt][3] + bv1);
        }
    }
#undef QKV_STAGE
#undef QKV_COMPUTE
}

// ---------------- persistent tensor-core LSTM (R9 design + fast gates) ------
constexpr int WHH_STR = 516;
constexpr int WIH_STR = 132;
constexpr int HS_STR  = 68;
constexpr int WHH_FLOATS = 64 * WHH_STR;
constexpr int WIH_FLOATS = 64 * WIH_STR;
constexpr int STG_FLOATS = 64 * HS_STR;
constexpr int LSTM_SMEM_BYTES = (WHH_FLOATS + WIH_FLOATS + 3 * STG_FLOATS) * 4;

__device__ __forceinline__ void lstm_comp(const float* HS, const float* WS,
                                          int wstr, int coff,
                                          int wm, int wn, int gq, int tg,
                                          float (&acc)[2][2][4]) {
#pragma unroll
    for (int ks = 0; ks < 64; ks += 8) {
        float a[2][4];
        float bf[2][2];
#pragma unroll
        for (int mt = 0; mt < 2; mt++) {
            int r = wm + mt * 16 + gq;
            int cc = ks + tg;
            a[mt][0] = HS[r * HS_STR + cc];
            a[mt][1] = HS[(r + 8) * HS_STR + cc];
            a[mt][2] = HS[r * HS_STR + cc + 4];
            a[mt][3] = HS[(r + 8) * HS_STR + cc + 4];
        }
#pragma unroll
        for (int nt = 0; nt < 2; nt++) {
            int n = wn + nt * 8 + gq;
            bf[nt][0] = WS[n * wstr + coff + ks + tg];
            bf[nt][1] = WS[n * wstr + coff + ks + tg + 4];
        }
#pragma unroll
        for (int mt = 0; mt < 2; mt++)
#pragma unroll
            for (int nt = 0; nt < 2; nt++)
                mma_tf32(acc[mt][nt], a[mt][0], a[mt][1], a[mt][2], a[mt][3],
                         bf[nt][0], bf[nt][1]);
    }
}

__global__ __launch_bounds__(256, 1)
void lstm_persistent(const float* __restrict__ w_ih,    // (4H,E)
                     const float* __restrict__ w_hh,    // (4H,H)
                     const int* __restrict__ lengths) {
    extern __shared__ __align__(16) float dsm[];
    float* ws_hh = dsm;
    float* ws_ih = ws_hh + WHH_FLOATS;
    float* stage = ws_ih + WIH_FLOATS;         // 3 buffers of STG_FLOATS
    float* ps    = stage + 1 * STG_FLOATS;     // alias buffer 1

    const int tid = threadIdx.x;
    const int lane = tid & 31;
    const int wid = tid >> 5;
    const int wm = (wid & 1) * 32;
    const int wn = (wid >> 1) * 16;
    const int j0 = (blockIdx.x & 31) * 16;
    const int b0 = (blockIdx.x >> 5) * 64;
    const int grp = blockIdx.x >> 5;

    const int gq = lane >> 2;
    const int tg = lane & 3;

    for (int idx = tid; idx < 64 * 128; idx += 256) {
        int n = idx >> 7;
        int k4 = (idx & 127) * 4;
        int g = n >> 4, jl = n & 15;
        float4 v = *(const float4*)(w_hh + (size_t)(g * H_ + j0 + jl) * H_ + k4);
        float* dst = ws_hh + n * WHH_STR + k4;
        dst[0] = tf32r(v.x); dst[1] = tf32r(v.y);
        dst[2] = tf32r(v.z); dst[3] = tf32r(v.w);
    }
    for (int idx = tid; idx < 64 * 32; idx += 256) {
        int n = idx >> 5;
        int k4 = (idx & 31) * 4;
        int g = n >> 4, jl = n & 15;
        float4 v = *(const float4*)(w_ih + (size_t)(g * H_ + j0 + jl) * E_ + k4);
        float* dst = ws_ih + n * WIH_STR + k4;
        dst[0] = tf32r(v.x); dst[1] = tf32r(v.y);
        dst[2] = tf32r(v.z); dst[3] = tf32r(v.w);
    }
    __syncthreads();

    const int row = tid >> 2;
    const int cg = tid & 3;
    const float* e_base = g_embs + (size_t)(b0 + row) * E_ + cg * 16;
    const float* h_base = g_hseq + (size_t)(b0 + row) * H_ + cg * 16;

    uint32_t stage_u32 = (uint32_t)__cvta_generic_to_shared(stage);
    uint32_t stg_u32[3];
#pragma unroll
    for (int bff = 0; bff < 3; bff++)
        stg_u32[bff] = stage_u32 + (uint32_t)(bff * STG_FLOATS + row * HS_STR + cg * 16) * 4u;

    int lenp[4];
    float bi[4], bfo[4], bg[4], bo4[4];
    float creg[4];
#pragma unroll
    for (int p = 0; p < 4; p++) {
        int idx = tid + p * 256;
        int jloc = idx & 15;
        int bl = idx >> 4;
        lenp[p] = lengths[b0 + bl];
        int j = j0 + jloc;
        bi[p]  = g_bsum[j];
        bfo[p] = g_bsum[H_ + j];
        bg[p]  = g_bsum[2 * H_ + j];
        bo4[p] = g_bsum[3 * H_ + j];
        creg[p] = 0.f;
    }

    for (int t = 0; t < T_; t++) {
        const float* e_t = e_base + (size_t)t * B_ * E_;
        const float* h_t = h_base + (size_t)t * B_ * H_;

        auto issue = [&](int c, uint32_t dst) {
            const float* s = (c < 2) ? (e_t + c * 64) : (h_t + (c - 2) * 64);
            cp16(dst, s); cp16(dst + 16, s + 4);
            cp16(dst + 32, s + 8); cp16(dst + 48, s + 12);
            cp_commit();
        };

        float acc[2][2][4];
#pragma unroll
        for (int mt = 0; mt < 2; mt++)
#pragma unroll
            for (int nt = 0; nt < 2; nt++)
#pragma unroll
                for (int q = 0; q < 4; q++) acc[mt][nt][q] = 0.f;

        issue(0, stg_u32[0]);
        issue(1, stg_u32[1]);

#pragma unroll
        for (int c = 0; c < 10; c++) {
            if (c < 9) cp_wait<1>(); else cp_wait<0>();
            __syncthreads();
            if (c + 2 < 10) issue(c + 2, stg_u32[(c + 2) % 3]);
            const float* HS = stage + (c % 3) * STG_FLOATS;
            if (c < 2)
                lstm_comp(HS, ws_ih, WIH_STR, c * 64, wm, wn, gq, tg, acc);
            else
                lstm_comp(HS, ws_hh, WHH_STR, (c - 2) * 64, wm, wn, gq, tg, acc);
        }

        __syncthreads();
#pragma unroll
        for (int mt = 0; mt < 2; mt++) {
            int r = wm + mt * 16 + gq;
#pragma unroll
            for (int nt = 0; nt < 2; nt++) {
                int c = wn + nt * 8 + 2 * tg;
                *(float2*)&ps[r * HS_STR + c] = make_float2(acc[mt][nt][0], acc[mt][nt][1]);
                *(float2*)&ps[(r + 8) * HS_STR + c] = make_float2(acc[mt][nt][2], acc[mt][nt][3]);
            }
        }
        __syncthreads();

        float* hout = g_hseq + (size_t)(t + 1) * B_ * H_;
#pragma unroll
        for (int p = 0; p < 4; p++) {
            int idx = tid + p * 256;
            int jloc = idx & 15;
            int bl = idx >> 4;
            int b = b0 + bl;
            int j = j0 + jloc;
            float gi = sigmoid_fast(ps[bl * HS_STR + jloc]      + bi[p]);
            float gf = sigmoid_fast(ps[bl * HS_STR + 16 + jloc] + bfo[p]);
            float gg = tanh_fast(   ps[bl * HS_STR + 32 + jloc] + bg[p]);
            float go = sigmoid_fast(ps[bl * HS_STR + 48 + jloc] + bo4[p]);
            float cn = gf * creg[p] + gi * gg;
            creg[p] = cn;
            float hn = tf32r(go * tanh_fast(cn));
            hout[(size_t)b * H_ + j] = hn;
            g_lstm_out[(size_t)(b * T_ + t) * H_ + j] = (t < lenp[p]) ? hn : 0.f;
        }
        __syncthreads();

        if (t != T_ - 1) {
            if (tid == 0) {
                __threadfence();
                atomicAdd(&g_bar4[grp * 16], 1u);
                unsigned target = 32u * (unsigned)(t + 1);
                volatile unsigned* vb = &g_bar4[grp * 16];
                while (*vb < target) __nanosleep(32);
            }
            __syncthreads();
        }
    }
}

// ---------------- attention + in-block t-pooling -----------------------------
__global__ __launch_bounds__(256)
void attention_kernel(const float* __restrict__ QKV,
                      const int* __restrict__ lengths,
                      float* __restrict__ poolw) {
    __shared__ float qs[64 * 64];
    __shared__ float ks[64 * 64];
    __shared__ float ss[64 * 64];
    const int b = blockIdx.x, nh = blockIdx.y;
    const int tid = threadIdx.x;
    const int len = lengths[b];
    const size_t qkvbase = ((size_t)b * 64) * 1536 + nh * 64;

#pragma unroll
    for (int l = 0; l < 4; l++) {
        int fidx = tid + (l << 8);
        int r = fidx & 63, c4 = fidx >> 6;
        float4 qv = *(const float4*)(QKV + qkvbase + (size_t)r * 1536 + c4 * 4);
        float4 kv = *(const float4*)(QKV + qkvbase + 512 + (size_t)r * 1536 + c4 * 4);
        qs[(c4 * 4 + 0) * 64 + r] = qv.x; qs[(c4 * 4 + 1) * 64 + r] = qv.y;
        qs[(c4 * 4 + 2) * 64 + r] = qv.z; qs[(c4 * 4 + 3) * 64 + r] = qv.w;
        ks[(c4 * 4 + 0) * 64 + r] = kv.x; ks[(c4 * 4 + 1) * 64 + r] = kv.y;
        ks[(c4 * 4 + 2) * 64 + r] = kv.z; ks[(c4 * 4 + 3) * 64 + r] = kv.w;
    }
    __syncthreads();

    const int tx = tid & 15, ty = tid >> 4;
    const int r0 = ty * 4, c0 = tx * 4;
    float acc[4][4];
#pragma unroll
    for (int i = 0; i < 4; i++)
#pragma unroll
        for (int j = 0; j < 4; j++) acc[i][j] = 0.f;

#pragma unroll 8
    for (int k = 0; k < 64; k++) {
        float4 aq = *(const float4*)&qs[k * 64 + r0];
        float4 bk = *(const float4*)&ks[k * 64 + c0];
        float a[4] = {aq.x, aq.y, aq.z, aq.w};
        float bb[4] = {bk.x, bk.y, bk.z, bk.w};
#pragma unroll
        for (int i = 0; i < 4; i++)
#pragma unroll
            for (int j = 0; j < 4; j++) acc[i][j] += a[i] * bb[j];
    }
#pragma unroll
    for (int i = 0; i < 4; i++)
#pragma unroll
        for (int j = 0; j < 4; j++) {
            int c = c0 + j;
            ss[(r0 + i) * 64 + c] = (c < len) ? acc[i][j] * 0.125f : -1e30f;
        }
    __syncthreads();

    float* vs = qs;
#pragma unroll
    for (int l = 0; l < 4; l++) {
        int fidx = tid + (l << 8);
        int r = fidx >> 4, c4 = fidx & 15;
        ((float4*)vs)[fidx] =
            *(const float4*)(QKV + qkvbase + 1024 + (size_t)r * 1536 + c4 * 4);
    }
    if (tid < 64) {
        float m = -1e30f;
#pragma unroll 8
        for (int c = 0; c < 64; c++) m = fmaxf(m, ss[tid * 64 + c]);
        float s = 0.f;
#pragma unroll 8
        for (int c = 0; c < 64; c++) {
            float e = __expf(ss[tid * 64 + c] - m);
            ss[tid * 64 + c] = e;
            s += e;
        }
        float inv = __fdividef(1.f, s);
#pragma unroll 8
        for (int c = 0; c < 64; c++) ss[tid * 64 + c] *= inv;
    }
    __syncthreads();

    float o[4][4];
#pragma unroll
    for (int i = 0; i < 4; i++)
#pragma unroll
        for (int j = 0; j < 4; j++) o[i][j] = 0.f;
#pragma unroll 8
    for (int k = 0; k < 64; k++) {
        float a[4];
#pragma unroll
        for (int i = 0; i < 4; i++) a[i] = ss[(r0 + i) * 64 + k];
        float4 vv4 = *(const float4*)&vs[k * 64 + c0];
        float vv[4] = {vv4.x, vv4.y, vv4.z, vv4.w};
#pragma unroll
        for (int i = 0; i < 4; i++)
#pragma unroll
            for (int j = 0; j < 4; j++) o[i][j] += a[i] * vv[j];
    }

    // pool over t (all 64 rows): reduce within block, write poolw slice
    __syncthreads();
#pragma unroll
    for (int j = 0; j < 4; j++)
        ss[ty * 64 + c0 + j] = o[0][j] + o[1][j] + o[2][j] + o[3][j];
    __syncthreads();
    if (tid < 64) {
        float s = 0.f;
#pragma unroll
        for (int g = 0; g < 16; g++) s += ss[g * 64 + tid];
        poolw[(size_t)b * H_ + nh * 64 + tid] = s * (1.f / 64.f);
    }
}

// ---------------- entry point -----------------------------------------------
extern "C" void kernel_launch(void* const* d_in, const int* in_sizes, int n_in,
                              void* d_out, int out_size) {
    const int*   x       = (const int*)d_in[0];
    const int*   lengths = (const int*)d_in[1];
    const float* emb     = (const float*)d_in[2];
    const float* w_ih    = (const float*)d_in[3];
    const float* w_hh    = (const float*)d_in[4];
    const float* b_ih    = (const float*)d_in[5];
    const float* b_hh    = (const float*)d_in[6];
    const float* wq      = (const float*)d_in[7];
    const float* bq      = (const float*)d_in[8];
    const float* wk      = (const float*)d_in[9];
    const float* bk      = (const float*)d_in[10];
    const float* wv      = (const float*)d_in[11];
    const float* bv      = (const float*)d_in[12];
    const float* wo      = (const float*)d_in[13];
    const float* bo      = (const float*)d_in[14];
    const float* w_h2e   = (const float*)d_in[15];
    const float* b_h2e   = (const float*)d_in[16];
    float* out = (float*)d_out;

    float *p_lo, *p_qkv, *p_pool, *p_ae;
    cudaGetSymbolAddress((void**)&p_lo,   g_lstm_out);
    cudaGetSymbolAddress((void**)&p_qkv,  g_QKV);
    cudaGetSymbolAddress((void**)&p_pool, g_poolw);
    cudaGetSymbolAddress((void**)&p_ae,   g_ae);

    static bool attr_set = false;
    if (!attr_set) {
        cudaFuncSetAttribute(lstm_persistent,
                             cudaFuncAttributeMaxDynamicSharedMemorySize,
                             LSTM_SMEM_BYTES);
        attr_set = true;
    }

    zero_init_kernel<<<(B_ * H_ + 255) / 256, 256>>>();
    bias_sum_kernel<<<(G4_ + 255) / 256, 256>>>(b_ih, b_hh);
    gather_square_kernel<<<(TB_ * E_ / 4 + 255) / 256, 256>>>(x, emb);
    combine_kernel<<<dim3(E_ / EPB, 16), 256>>>(wo, bo, w_h2e, b_h2e);

    // LSTM recurrence (R9 persistent design + fast gates)
    lstm_persistent<<<128, 256, LSTM_SMEM_BYTES>>>(w_ih, w_hh, lengths);

    // fused QKV projection -> [TB][1536]
    gemm_qkv<<<dim3(12, TB_ / 128), 256>>>(p_lo, wq, wk, wv, bq, bk, bv, p_qkv);

    // attention + in-block mean-pool over t -> poolw (B,H)
    attention_kernel<<<dim3(B_, NH_), 256>>>(p_qkv, lengths, p_pool);

    // ae = poolw @ Wc^T + bc  (combined O-proj + h2e)
    ae_kernel<<<B_, 128>>>();

    // final scores = ae @ emb^T
    gemm_tf32<true><<<dim3((NITEMS + 127) / 128, B_ / 128), 256>>>(p_ae, emb, nullptr, out, B_, NITEMS, E_);
}